// round 1
// baseline (speedup 1.0000x reference)
#include <cuda_runtime.h>
#include <cuda_bf16.h>

// Problem constants
#define TOK   8192          // B*N = 4*2048
#define SEQ   2048
#define BATCH 4
#define DIM   768
#define NHEAD 12
#define HDIM  64
#define BH    (BATCH*NHEAD) // 48
#define HID   3072
#define QKSCALE 0.125f      // 64^-0.5
#define LN_EPS 1e-5f

// -------- scratch (device globals; no allocation allowed) --------
__device__ float g_h[TOK * DIM];            // LN output (reused LN1/LN2)
__device__ float g_q[BH * SEQ * HDIM];
__device__ float g_k[BH * SEQ * HDIM];
__device__ float g_v[BH * SEQ * HDIM];
__device__ float g_attnout[TOK * DIM];
__device__ float g_x1[TOK * DIM];           // x after attention residual
__device__ float g_u[TOK * HID];            // fc1 output (post-gelu)

// ============================ LayerNorm ============================
__global__ __launch_bounds__(256) void ln_kernel(
    const float* __restrict__ x, const float* __restrict__ gamma,
    const float* __restrict__ beta, float* __restrict__ out)
{
    int row = blockIdx.x;
    const float* xr = x + (size_t)row * DIM;
    float s = 0.f, s2 = 0.f;
    for (int i = threadIdx.x; i < DIM; i += 256) {
        float v = xr[i]; s += v; s2 += v * v;
    }
    #pragma unroll
    for (int o = 16; o; o >>= 1) {
        s  += __shfl_xor_sync(0xffffffffu, s,  o);
        s2 += __shfl_xor_sync(0xffffffffu, s2, o);
    }
    __shared__ float rs[8], rs2[8];
    int lane = threadIdx.x & 31, wid = threadIdx.x >> 5;
    if (lane == 0) { rs[wid] = s; rs2[wid] = s2; }
    __syncthreads();
    float ts = 0.f, ts2 = 0.f;
    #pragma unroll
    for (int i = 0; i < 8; i++) { ts += rs[i]; ts2 += rs2[i]; }
    float mean = ts * (1.0f / DIM);
    float var  = ts2 * (1.0f / DIM) - mean * mean;
    float inv  = rsqrtf(var + LN_EPS);
    float* orow = out + (size_t)row * DIM;
    for (int i = threadIdx.x; i < DIM; i += 256)
        orow[i] = (xr[i] - mean) * inv * gamma[i] + beta[i];
}

// ============================ SGEMM ============================
// C[M,N] = A[M,K] @ W[K,N] (+bias) with epilogue:
//   EPI=1: scatter to q/k/v head-major buffers
//   EPI=2: + residual -> C
//   EPI=3: PolyGELU -> C     (coefs read from c0,c1,c2 pointers)
template <int EPI>
__global__ __launch_bounds__(256) void sgemm(
    const float* __restrict__ A, const float* __restrict__ W,
    const float* __restrict__ bias, const float* __restrict__ res,
    float* __restrict__ C, int M, int N, int K,
    float* __restrict__ qo, float* __restrict__ ko, float* __restrict__ vo,
    const float* __restrict__ c0, const float* __restrict__ c1,
    const float* __restrict__ c2)
{
    __shared__ float As[8][128];
    __shared__ float Bs[8][128];

    const int tid = threadIdx.x;
    const int tx = tid & 15, ty = tid >> 4;
    const int bx = blockIdx.x, by = blockIdx.y;

    const int rowA = by * 128 + (tid >> 1);
    const int kA   = (tid & 1) * 4;
    const int rowB = tid >> 5;
    const int colBl = (tid & 31) * 4;
    const int colB = bx * 128 + colBl;

    float acc[8][8];
    #pragma unroll
    for (int i = 0; i < 8; i++)
        #pragma unroll
        for (int j = 0; j < 8; j++) acc[i][j] = 0.f;

    for (int k0 = 0; k0 < K; k0 += 8) {
        float4 a4 = *(const float4*)(A + (size_t)rowA * K + k0 + kA);
        float4 b4 = *(const float4*)(W + (size_t)(k0 + rowB) * N + colB);
        __syncthreads();
        As[kA + 0][tid >> 1] = a4.x;
        As[kA + 1][tid >> 1] = a4.y;
        As[kA + 2][tid >> 1] = a4.z;
        As[kA + 3][tid >> 1] = a4.w;
        *(float4*)&Bs[rowB][colBl] = b4;
        __syncthreads();
        #pragma unroll
        for (int kk = 0; kk < 8; kk++) {
            float a[8], b[8];
            float4 av0 = *(const float4*)&As[kk][ty * 4];
            float4 av1 = *(const float4*)&As[kk][64 + ty * 4];
            float4 bv0 = *(const float4*)&Bs[kk][tx * 4];
            float4 bv1 = *(const float4*)&Bs[kk][64 + tx * 4];
            a[0]=av0.x; a[1]=av0.y; a[2]=av0.z; a[3]=av0.w;
            a[4]=av1.x; a[5]=av1.y; a[6]=av1.z; a[7]=av1.w;
            b[0]=bv0.x; b[1]=bv0.y; b[2]=bv0.z; b[3]=bv0.w;
            b[4]=bv1.x; b[5]=bv1.y; b[6]=bv1.z; b[7]=bv1.w;
            #pragma unroll
            for (int i = 0; i < 8; i++)
                #pragma unroll
                for (int j = 0; j < 8; j++)
                    acc[i][j] = fmaf(a[i], b[j], acc[i][j]);
        }
    }

    float ga = 0.f, gb = 0.f, gc = 0.f;
    if (EPI == 3) { ga = *c0; gb = *c1; gc = *c2; }

    #pragma unroll
    for (int i = 0; i < 8; i++) {
        int r = by * 128 + ((i < 4) ? (ty * 4 + i) : (64 + ty * 4 + i - 4));
        #pragma unroll
        for (int j = 0; j < 8; j++) {
            int c = bx * 128 + ((j < 4) ? (tx * 4 + j) : (64 + tx * 4 + j - 4));
            float v = acc[i][j] + bias[c];
            if (EPI == 1) {
                int which = c / DIM;
                int jj = c - which * DIM;
                int h = jj >> 6, d = jj & 63;
                int b = r >> 11, n = r & 2047;
                float* dst = (which == 0) ? qo : (which == 1) ? ko : vo;
                dst[(((size_t)(b * NHEAD + h) * SEQ) + n) * HDIM + d] = v;
            } else if (EPI == 2) {
                C[(size_t)r * N + c] = v + res[(size_t)r * N + c];
            } else if (EPI == 3) {
                C[(size_t)r * N + c] = fmaf(v, fmaf(ga, v, gb), gc); // a*v^2+b*v+c
            } else {
                C[(size_t)r * N + c] = v;
            }
        }
    }
}

// ============================ Polynomial attention ============================
// out[n,:] = (sum_m f(q.k*scale) * V[m,:]) / (sum_m f + 1e-8),
// f(s) = max(a*s^2 + b*s + c, 1e-6).  Single-pass flash-style (no softmax max).
__global__ __launch_bounds__(256) void attn_kernel(
    const float* __restrict__ Q, const float* __restrict__ Kg,
    const float* __restrict__ Vg, float* __restrict__ out,
    const float* __restrict__ pa, const float* __restrict__ pb,
    const float* __restrict__ pc)
{
    __shared__ float Qs[64 * 64];
    __shared__ float KVs[64 * 64];   // holds K^T, then V
    __shared__ float Ss[64 * 64];

    const int tid = threadIdx.x;
    const int tx = tid & 15, ty = tid >> 4;
    const int bh = blockIdx.y;
    const int n0 = blockIdx.x * 64;

    const float* Qb = Q  + (size_t)bh * SEQ * HDIM;
    const float* Kb = Kg + (size_t)bh * SEQ * HDIM;
    const float* Vb = Vg + (size_t)bh * SEQ * HDIM;

    const float aa = *pa, bb = *pb, cc = *pc;

    // load Q tile, pre-scaled
    for (int i = tid; i < 1024; i += 256) {
        int idx = i * 4; int r = idx >> 6; int d = idx & 63;
        float4 v = *(const float4*)(Qb + (size_t)(n0 + r) * HDIM + d);
        v.x *= QKSCALE; v.y *= QKSCALE; v.z *= QKSCALE; v.w *= QKSCALE;
        *(float4*)&Qs[r * 64 + d] = v;
    }

    float o[4][4];
    #pragma unroll
    for (int i = 0; i < 4; i++)
        #pragma unroll
        for (int j = 0; j < 4; j++) o[i][j] = 0.f;
    float rsum[4] = {0.f, 0.f, 0.f, 0.f};

    for (int m0 = 0; m0 < SEQ; m0 += 64) {
        __syncthreads();  // prior S@V reads of KVs / Ss done
        // load K tile transposed: KVs[d][m]
        for (int i = tid; i < 1024; i += 256) {
            int idx = i * 4; int r = idx >> 6; int d = idx & 63;
            float4 v = *(const float4*)(Kb + (size_t)(m0 + r) * HDIM + d);
            KVs[(d + 0) * 64 + r] = v.x;
            KVs[(d + 1) * 64 + r] = v.y;
            KVs[(d + 2) * 64 + r] = v.z;
            KVs[(d + 3) * 64 + r] = v.w;
        }
        __syncthreads();

        float s[4][4];
        #pragma unroll
        for (int i = 0; i < 4; i++)
            #pragma unroll
            for (int j = 0; j < 4; j++) s[i][j] = 0.f;

        #pragma unroll 8
        for (int d = 0; d < 64; d++) {
            float qr[4], kr[4];
            #pragma unroll
            for (int i = 0; i < 4; i++) qr[i] = Qs[(ty * 4 + i) * 64 + d];
            #pragma unroll
            for (int j = 0; j < 4; j++) kr[j] = KVs[d * 64 + tx * 4 + j];
            #pragma unroll
            for (int i = 0; i < 4; i++)
                #pragma unroll
                for (int j = 0; j < 4; j++)
                    s[i][j] = fmaf(qr[i], kr[j], s[i][j]);
        }

        __syncthreads();  // all S reads of KVs (K) done before overwrite with V

        float rl[4] = {0.f, 0.f, 0.f, 0.f};
        #pragma unroll
        for (int i = 0; i < 4; i++) {
            #pragma unroll
            for (int j = 0; j < 4; j++) {
                float t = s[i][j];
                t = fmaf(t, fmaf(aa, t, bb), cc);   // a*t^2 + b*t + c
                t = fmaxf(t, 1e-6f);
                Ss[(ty * 4 + i) * 64 + tx * 4 + j] = t;
                rl[i] += t;
            }
        }
        // reduce row partials across the 16 tx lanes (stays within 16-lane half)
        #pragma unroll
        for (int off = 1; off < 16; off <<= 1)
            #pragma unroll
            for (int i = 0; i < 4; i++)
                rl[i] += __shfl_xor_sync(0xffffffffu, rl[i], off);
        if (tx == 0)
            #pragma unroll
            for (int i = 0; i < 4; i++) rsum[i] += rl[i];

        // load V tile (normal layout) into KVs
        for (int i = tid; i < 1024; i += 256) {
            int idx = i * 4; int r = idx >> 6; int d = idx & 63;
            *(float4*)&KVs[r * 64 + d] =
                *(const float4*)(Vb + (size_t)(m0 + r) * HDIM + d);
        }
        __syncthreads();

        // o += Ss @ V
        #pragma unroll 8
        for (int m = 0; m < 64; m++) {
            float sr[4], vr[4];
            #pragma unroll
            for (int i = 0; i < 4; i++) sr[i] = Ss[(ty * 4 + i) * 64 + m];
            #pragma unroll
            for (int j = 0; j < 4; j++) vr[j] = KVs[m * 64 + tx * 4 + j];
            #pragma unroll
            for (int i = 0; i < 4; i++)
                #pragma unroll
                for (int j = 0; j < 4; j++)
                    o[i][j] = fmaf(sr[i], vr[j], o[i][j]);
        }
    }

    __syncthreads();
    if (tx == 0)
        #pragma unroll
        for (int i = 0; i < 4; i++) Ss[ty * 4 + i] = rsum[i];
    __syncthreads();

    int b = bh / NHEAD, h = bh % NHEAD;
    #pragma unroll
    for (int i = 0; i < 4; i++) {
        float inv = 1.0f / (Ss[ty * 4 + i] + 1e-8f);
        int n = n0 + ty * 4 + i;
        size_t base = ((size_t)(b * SEQ + n)) * DIM + h * HDIM + tx * 4;
        #pragma unroll
        for (int j = 0; j < 4; j++)
            out[base + j] = o[i][j] * inv;
    }
}

// ============================ launch ============================
extern "C" void kernel_launch(void* const* d_in, const int* in_sizes, int n_in,
                              void* d_out, int out_size)
{
    const float* x      = (const float*)d_in[0];
    const float* ln1_g  = (const float*)d_in[1];
    const float* ln1_b  = (const float*)d_in[2];
    const float* ln2_g  = (const float*)d_in[3];
    const float* ln2_b  = (const float*)d_in[4];
    const float* qkv_w  = (const float*)d_in[5];
    const float* qkv_b  = (const float*)d_in[6];
    const float* proj_w = (const float*)d_in[7];
    const float* proj_b = (const float*)d_in[8];
    const float* fc1_w  = (const float*)d_in[9];
    const float* fc1_b  = (const float*)d_in[10];
    const float* fc2_w  = (const float*)d_in[11];
    const float* fc2_b  = (const float*)d_in[12];
    const float* attn_a = (const float*)d_in[13];
    const float* attn_b = (const float*)d_in[14];
    const float* attn_c = (const float*)d_in[15];
    const float* gelu_a = (const float*)d_in[16];
    const float* gelu_b = (const float*)d_in[17];
    const float* gelu_c = (const float*)d_in[18];
    float* out = (float*)d_out;

    void *p_h, *p_q, *p_k, *p_v, *p_ao, *p_x1, *p_u;
    cudaGetSymbolAddress(&p_h,  g_h);
    cudaGetSymbolAddress(&p_q,  g_q);
    cudaGetSymbolAddress(&p_k,  g_k);
    cudaGetSymbolAddress(&p_v,  g_v);
    cudaGetSymbolAddress(&p_ao, g_attnout);
    cudaGetSymbolAddress(&p_x1, g_x1);
    cudaGetSymbolAddress(&p_u,  g_u);
    float* h_  = (float*)p_h;
    float* q_  = (float*)p_q;
    float* k_  = (float*)p_k;
    float* v_  = (float*)p_v;
    float* ao_ = (float*)p_ao;
    float* x1_ = (float*)p_x1;
    float* u_  = (float*)p_u;

    // 1. LN1
    ln_kernel<<<TOK, 256>>>(x, ln1_g, ln1_b, h_);
    // 2. QKV GEMM with head-major scatter
    sgemm<1><<<dim3(3 * DIM / 128, TOK / 128), 256>>>(
        h_, qkv_w, qkv_b, nullptr, nullptr, TOK, 3 * DIM, DIM,
        q_, k_, v_, nullptr, nullptr, nullptr);
    // 3. polynomial attention (fused, single pass)
    attn_kernel<<<dim3(SEQ / 64, BH), 256>>>(q_, k_, v_, ao_,
                                             attn_a, attn_b, attn_c);
    // 4. proj GEMM + residual -> x1
    sgemm<2><<<dim3(DIM / 128, TOK / 128), 256>>>(
        ao_, proj_w, proj_b, x, x1_, TOK, DIM, DIM,
        nullptr, nullptr, nullptr, nullptr, nullptr, nullptr);
    // 5. LN2
    ln_kernel<<<TOK, 256>>>(x1_, ln2_g, ln2_b, h_);
    // 6. FC1 GEMM + PolyGELU
    sgemm<3><<<dim3(HID / 128, TOK / 128), 256>>>(
        h_, fc1_w, fc1_b, nullptr, u_, TOK, HID, DIM,
        nullptr, nullptr, nullptr, gelu_a, gelu_b, gelu_c);
    // 7. FC2 GEMM + residual -> out
    sgemm<2><<<dim3(DIM / 128, TOK / 128), 256>>>(
        u_, fc2_w, fc2_b, x1_, out, TOK, DIM, HID,
        nullptr, nullptr, nullptr, nullptr, nullptr, nullptr);
}

// round 2
// speedup vs baseline: 2.7131x; 2.7131x over previous
#include <cuda_runtime.h>
#include <cuda_bf16.h>

// Problem constants
#define TOK   8192          // B*N = 4*2048
#define SEQ   2048
#define BATCH 4
#define DIM   768
#define NHEAD 12
#define HDIM  64
#define BH    (BATCH*NHEAD) // 48
#define HID   3072
#define QKSCALE 0.125f      // 64^-0.5
#define LN_EPS 1e-5f

// -------- scratch (device globals; no allocation allowed) --------
__device__ float g_h[TOK * DIM];
__device__ float g_q[BH * SEQ * HDIM];
__device__ float g_k[BH * SEQ * HDIM];
__device__ float g_v[BH * SEQ * HDIM];
__device__ float g_attnout[TOK * DIM];
__device__ float g_x1[TOK * DIM];
__device__ float g_u[TOK * HID];

// ---------- helpers ----------
__device__ __forceinline__ unsigned f2tf(float x) {
    unsigned r;
    asm("cvt.rna.tf32.f32 %0, %1;" : "=r"(r) : "f"(x));
    return r;
}

__device__ __forceinline__ void mma_tf32(float& d0, float& d1, float& d2, float& d3,
                                         unsigned a0, unsigned a1, unsigned a2, unsigned a3,
                                         unsigned b0, unsigned b1)
{
    asm volatile(
        "mma.sync.aligned.m16n8k8.row.col.f32.tf32.tf32.f32 "
        "{%0,%1,%2,%3},{%4,%5,%6,%7},{%8,%9},{%0,%1,%2,%3};"
        : "+f"(d0), "+f"(d1), "+f"(d2), "+f"(d3)
        : "r"(a0), "r"(a1), "r"(a2), "r"(a3), "r"(b0), "r"(b1));
}

// ============================ LayerNorm ============================
__global__ __launch_bounds__(256) void ln_kernel(
    const float* __restrict__ x, const float* __restrict__ gamma,
    const float* __restrict__ beta, float* __restrict__ out)
{
    int row = blockIdx.x;
    const float* xr = x + (size_t)row * DIM;
    float s = 0.f, s2 = 0.f;
    for (int i = threadIdx.x; i < DIM; i += 256) {
        float v = xr[i]; s += v; s2 += v * v;
    }
    #pragma unroll
    for (int o = 16; o; o >>= 1) {
        s  += __shfl_xor_sync(0xffffffffu, s,  o);
        s2 += __shfl_xor_sync(0xffffffffu, s2, o);
    }
    __shared__ float rs[8], rs2[8];
    int lane = threadIdx.x & 31, wid = threadIdx.x >> 5;
    if (lane == 0) { rs[wid] = s; rs2[wid] = s2; }
    __syncthreads();
    float ts = 0.f, ts2 = 0.f;
    #pragma unroll
    for (int i = 0; i < 8; i++) { ts += rs[i]; ts2 += rs2[i]; }
    float mean = ts * (1.0f / DIM);
    float var  = ts2 * (1.0f / DIM) - mean * mean;
    float inv  = rsqrtf(var + LN_EPS);
    float* orow = out + (size_t)row * DIM;
    for (int i = threadIdx.x; i < DIM; i += 256)
        orow[i] = (xr[i] - mean) * inv * gamma[i] + beta[i];
}

// ============================ TF32 tensor-core GEMM ============================
// C[M,N] = A[M,K] @ W[K,N] + bias, epilogues as before.
// Block 128x128, 8 warps, warp tile 64x32, k-step 16.
template <int EPI>
__global__ __launch_bounds__(256) void mma_gemm(
    const float* __restrict__ A, const float* __restrict__ W,
    const float* __restrict__ bias, const float* __restrict__ res,
    float* __restrict__ C, int M, int N, int K,
    float* __restrict__ qo, float* __restrict__ ko, float* __restrict__ vo,
    const float* __restrict__ c0, const float* __restrict__ c1,
    const float* __restrict__ c2)
{
    __shared__ unsigned As[128 * 20];   // A tile [128][16], ld=20 (conflict-free frag loads)
    __shared__ unsigned Bs[16 * 136];   // B tile [16][128], ld=136

    const int tid  = threadIdx.x;
    const int lane = tid & 31;
    const int w    = tid >> 5;
    const int wm   = w >> 2;            // 0..1
    const int wn   = w & 3;             // 0..3
    const int bx = blockIdx.x, by = blockIdx.y;

    // global load mapping
    const int arow = tid >> 2;          // 0..63 (and +64)
    const int ac4  = tid & 3;           // float4 index in k16
    const int brow = tid >> 5;          // 0..7 (and +8)
    const int bc4  = tid & 31;          // float4 index in 128 cols

    const float* Aptr = A + (size_t)(by * 128 + arow) * K + ac4 * 4;
    const float* Bptr = W + (size_t)brow * N + bx * 128 + bc4 * 4;

    float acc[4][4][4];
    #pragma unroll
    for (int i = 0; i < 4; i++)
        #pragma unroll
        for (int j = 0; j < 4; j++)
            #pragma unroll
            for (int r = 0; r < 4; r++) acc[i][j][r] = 0.f;

    float4 ra0 = *(const float4*)(Aptr);
    float4 ra1 = *(const float4*)(Aptr + (size_t)64 * K);
    float4 rb0 = *(const float4*)(Bptr);
    float4 rb1 = *(const float4*)(Bptr + (size_t)8 * N);

    for (int k0 = 0; k0 < K; k0 += 16) {
        __syncthreads();
        // store tiles (convert to tf32)
        {
            unsigned* pa = As + arow * 20 + ac4 * 4;
            pa[0] = f2tf(ra0.x); pa[1] = f2tf(ra0.y); pa[2] = f2tf(ra0.z); pa[3] = f2tf(ra0.w);
            unsigned* pa2 = As + (arow + 64) * 20 + ac4 * 4;
            pa2[0] = f2tf(ra1.x); pa2[1] = f2tf(ra1.y); pa2[2] = f2tf(ra1.z); pa2[3] = f2tf(ra1.w);
            unsigned* pb = Bs + brow * 136 + bc4 * 4;
            pb[0] = f2tf(rb0.x); pb[1] = f2tf(rb0.y); pb[2] = f2tf(rb0.z); pb[3] = f2tf(rb0.w);
            unsigned* pb2 = Bs + (brow + 8) * 136 + bc4 * 4;
            pb2[0] = f2tf(rb1.x); pb2[1] = f2tf(rb1.y); pb2[2] = f2tf(rb1.z); pb2[3] = f2tf(rb1.w);
        }
        __syncthreads();
        // prefetch next k-tile
        if (k0 + 16 < K) {
            Aptr += 16;
            Bptr += (size_t)16 * N;
            ra0 = *(const float4*)(Aptr);
            ra1 = *(const float4*)(Aptr + (size_t)64 * K);
            rb0 = *(const float4*)(Bptr);
            rb1 = *(const float4*)(Bptr + (size_t)8 * N);
        }
        // compute: two k8 chunks
        #pragma unroll
        for (int kk = 0; kk < 16; kk += 8) {
            unsigned af[4][4], bf[4][2];
            #pragma unroll
            for (int mt = 0; mt < 4; mt++) {
                int r = wm * 64 + mt * 16 + (lane >> 2);
                int c = kk + (lane & 3);
                af[mt][0] = As[r * 20 + c];
                af[mt][1] = As[(r + 8) * 20 + c];
                af[mt][2] = As[r * 20 + c + 4];
                af[mt][3] = As[(r + 8) * 20 + c + 4];
            }
            #pragma unroll
            for (int nt = 0; nt < 4; nt++) {
                int col = wn * 32 + nt * 8 + (lane >> 2);
                bf[nt][0] = Bs[(kk + (lane & 3)) * 136 + col];
                bf[nt][1] = Bs[(kk + (lane & 3) + 4) * 136 + col];
            }
            #pragma unroll
            for (int mt = 0; mt < 4; mt++)
                #pragma unroll
                for (int nt = 0; nt < 4; nt++)
                    mma_tf32(acc[mt][nt][0], acc[mt][nt][1], acc[mt][nt][2], acc[mt][nt][3],
                             af[mt][0], af[mt][1], af[mt][2], af[mt][3],
                             bf[nt][0], bf[nt][1]);
        }
    }

    float ga = 0.f, gb = 0.f, gc = 0.f;
    if (EPI == 3) { ga = *c0; gb = *c1; gc = *c2; }

    // epilogue: C frag layout rows (l>>2, +8), cols 2*(l&3), +1
    #pragma unroll
    for (int mt = 0; mt < 4; mt++) {
        #pragma unroll
        for (int nt = 0; nt < 4; nt++) {
            int r0 = by * 128 + wm * 64 + mt * 16 + (lane >> 2);
            int cc0 = bx * 128 + wn * 32 + nt * 8 + 2 * (lane & 3);
            #pragma unroll
            for (int half = 0; half < 2; half++) {
                int r = r0 + half * 8;
                float v0 = acc[mt][nt][half * 2 + 0] + bias[cc0];
                float v1 = acc[mt][nt][half * 2 + 1] + bias[cc0 + 1];
                if (EPI == 1) {
                    int which = cc0 / DIM;
                    int jj = cc0 - which * DIM;
                    int h = jj >> 6, d = jj & 63;
                    int b = r >> 11, n = r & 2047;
                    float* dst = (which == 0) ? qo : (which == 1) ? ko : vo;
                    size_t base = (((size_t)(b * NHEAD + h) * SEQ) + n) * HDIM + d;
                    dst[base] = v0; dst[base + 1] = v1;
                } else if (EPI == 2) {
                    size_t base = (size_t)r * N + cc0;
                    C[base]     = v0 + res[base];
                    C[base + 1] = v1 + res[base + 1];
                } else if (EPI == 3) {
                    size_t base = (size_t)r * N + cc0;
                    C[base]     = fmaf(v0, fmaf(ga, v0, gb), gc);
                    C[base + 1] = fmaf(v1, fmaf(ga, v1, gb), gc);
                } else {
                    size_t base = (size_t)r * N + cc0;
                    C[base] = v0; C[base + 1] = v1;
                }
            }
        }
    }
}

// ============================ Polynomial attention (tensor cores) ============================
// One block = 64 query rows of one (b,h). 8 warps: warp w -> m-tile mt=w>>1 (16 rows),
// column half nh=w&1 (32 cols). Single pass: O += f(S)*V, rowsum += f(S).
__global__ __launch_bounds__(256) void attn_mma(
    const float* __restrict__ Q, const float* __restrict__ Kg,
    const float* __restrict__ Vg, float* __restrict__ out,
    const float* __restrict__ pa, const float* __restrict__ pb,
    const float* __restrict__ pc)
{
    __shared__ unsigned KVs[64 * 68];   // K tile [key][d] (A-pattern), then V^T [d][key]
    __shared__ unsigned Ss[64 * 68];    // Q staging, then f(S) tile
    __shared__ float rsums[64];

    const int tid  = threadIdx.x;
    const int lane = tid & 31;
    const int w    = tid >> 5;
    const int mt   = w >> 1;            // 0..3
    const int nh   = w & 1;             // 0..1
    const int bh   = blockIdx.y;
    const int n0   = blockIdx.x * 64;

    const float* Qb = Q  + (size_t)bh * SEQ * HDIM;
    const float* Kb = Kg + (size_t)bh * SEQ * HDIM;
    const float* Vb = Vg + (size_t)bh * SEQ * HDIM;

    const float aa = *pa, bb = *pb, cc = *pc;

    if (tid < 64) rsums[tid] = 0.f;

    // stage Q (scaled, tf32) into Ss
    #pragma unroll
    for (int it = 0; it < 4; it++) {
        int s = it * 256 + tid;
        int r = s >> 4, c4 = s & 15;
        float4 v = *(const float4*)(Qb + (size_t)(n0 + r) * HDIM + c4 * 4);
        unsigned* p = Ss + r * 68 + c4 * 4;
        p[0] = f2tf(v.x * QKSCALE); p[1] = f2tf(v.y * QKSCALE);
        p[2] = f2tf(v.z * QKSCALE); p[3] = f2tf(v.w * QKSCALE);
    }
    __syncthreads();

    // Q fragments resident in registers (warp's 16 rows, all 64 d)
    unsigned qf[8][4];
    #pragma unroll
    for (int kk = 0; kk < 8; kk++) {
        int r = mt * 16 + (lane >> 2);
        int c = kk * 8 + (lane & 3);
        qf[kk][0] = Ss[r * 68 + c];
        qf[kk][1] = Ss[(r + 8) * 68 + c];
        qf[kk][2] = Ss[r * 68 + c + 4];
        qf[kk][3] = Ss[(r + 8) * 68 + c + 4];
    }

    float oacc[4][4];
    #pragma unroll
    for (int nt = 0; nt < 4; nt++)
        #pragma unroll
        for (int r = 0; r < 4; r++) oacc[nt][r] = 0.f;
    float rs0 = 0.f, rs1 = 0.f;

    for (int m0 = 0; m0 < SEQ; m0 += 64) {
        __syncthreads();   // Q frags read / prior O-phase reads done
        // load K tile [key][d] (tf32)
        #pragma unroll
        for (int it = 0; it < 4; it++) {
            int s = it * 256 + tid;
            int r = s >> 4, c4 = s & 15;
            float4 v = *(const float4*)(Kb + (size_t)(m0 + r) * HDIM + c4 * 4);
            unsigned* p = KVs + r * 68 + c4 * 4;
            p[0] = f2tf(v.x); p[1] = f2tf(v.y); p[2] = f2tf(v.z); p[3] = f2tf(v.w);
        }
        __syncthreads();

        // S = Q K^T  (warp: 16 rows x 32 cols)
        float sacc[4][4];
        #pragma unroll
        for (int nt = 0; nt < 4; nt++)
            #pragma unroll
            for (int r = 0; r < 4; r++) sacc[nt][r] = 0.f;

        #pragma unroll
        for (int kk = 0; kk < 8; kk++) {
            unsigned bf[4][2];
            #pragma unroll
            for (int nt = 0; nt < 4; nt++) {
                int col = nh * 32 + nt * 8 + (lane >> 2);       // key index
                bf[nt][0] = KVs[col * 68 + kk * 8 + (lane & 3)];
                bf[nt][1] = KVs[col * 68 + kk * 8 + (lane & 3) + 4];
            }
            #pragma unroll
            for (int nt = 0; nt < 4; nt++)
                mma_tf32(sacc[nt][0], sacc[nt][1], sacc[nt][2], sacc[nt][3],
                         qf[kk][0], qf[kk][1], qf[kk][2], qf[kk][3],
                         bf[nt][0], bf[nt][1]);
        }

        // f(S) + rowsum partials
        #pragma unroll
        for (int nt = 0; nt < 4; nt++) {
            #pragma unroll
            for (int r = 0; r < 4; r++) {
                float t = sacc[nt][r];
                t = fmaf(t, fmaf(aa, t, bb), cc);
                t = fmaxf(t, 1e-6f);
                sacc[nt][r] = t;
                if (r < 2) rs0 += t; else rs1 += t;
            }
        }

        __syncthreads();   // all warps done reading K before overwrite with V^T

        // store f(S) to Ss (tf32)
        #pragma unroll
        for (int nt = 0; nt < 4; nt++) {
            int row = mt * 16 + (lane >> 2);
            int col = nh * 32 + nt * 8 + 2 * (lane & 3);
            Ss[row * 68 + col]           = f2tf(sacc[nt][0]);
            Ss[row * 68 + col + 1]       = f2tf(sacc[nt][1]);
            Ss[(row + 8) * 68 + col]     = f2tf(sacc[nt][2]);
            Ss[(row + 8) * 68 + col + 1] = f2tf(sacc[nt][3]);
        }

        // load V tile transposed: KVs[d][key]
        #pragma unroll
        for (int it = 0; it < 4; it++) {
            int s = it * 256 + tid;
            int r = s & 63;             // key
            int c4 = s >> 6;            // d/4
            float4 v = *(const float4*)(Vb + (size_t)(m0 + r) * HDIM + c4 * 4);
            KVs[(c4 * 4 + 0) * 68 + r] = f2tf(v.x);
            KVs[(c4 * 4 + 1) * 68 + r] = f2tf(v.y);
            KVs[(c4 * 4 + 2) * 68 + r] = f2tf(v.z);
            KVs[(c4 * 4 + 3) * 68 + r] = f2tf(v.w);
        }
        __syncthreads();

        // O += f(S) @ V   (warp: 16 rows x 32 head-dims)
        #pragma unroll
        for (int kk = 0; kk < 8; kk++) {
            unsigned af[4], bf[4][2];
            int r = mt * 16 + (lane >> 2);
            int c = kk * 8 + (lane & 3);
            af[0] = Ss[r * 68 + c];
            af[1] = Ss[(r + 8) * 68 + c];
            af[2] = Ss[r * 68 + c + 4];
            af[3] = Ss[(r + 8) * 68 + c + 4];
            #pragma unroll
            for (int nt = 0; nt < 4; nt++) {
                int col = nh * 32 + nt * 8 + (lane >> 2);       // head dim
                bf[nt][0] = KVs[col * 68 + kk * 8 + (lane & 3)];
                bf[nt][1] = KVs[col * 68 + kk * 8 + (lane & 3) + 4];
            }
            #pragma unroll
            for (int nt = 0; nt < 4; nt++)
                mma_tf32(oacc[nt][0], oacc[nt][1], oacc[nt][2], oacc[nt][3],
                         af[0], af[1], af[2], af[3],
                         bf[nt][0], bf[nt][1]);
        }
    }

    // rowsum reduction: lanes sharing a row are l%4 groups
    rs0 += __shfl_xor_sync(0xffffffffu, rs0, 1);
    rs0 += __shfl_xor_sync(0xffffffffu, rs0, 2);
    rs1 += __shfl_xor_sync(0xffffffffu, rs1, 1);
    rs1 += __shfl_xor_sync(0xffffffffu, rs1, 2);
    if ((lane & 3) == 0) {
        atomicAdd(&rsums[mt * 16 + (lane >> 2)], rs0);
        atomicAdd(&rsums[mt * 16 + (lane >> 2) + 8], rs1);
    }
    __syncthreads();

    // epilogue: normalize, write to [b, n, h*64 + d]
    int b = bh / NHEAD, h = bh % NHEAD;
    int row0 = mt * 16 + (lane >> 2);
    float inv0 = 1.0f / (rsums[row0] + 1e-8f);
    float inv1 = 1.0f / (rsums[row0 + 8] + 1e-8f);
    #pragma unroll
    for (int nt = 0; nt < 4; nt++) {
        int d = nh * 32 + nt * 8 + 2 * (lane & 3);
        size_t base0 = ((size_t)(b * SEQ + n0 + row0)) * DIM + h * HDIM + d;
        size_t base1 = ((size_t)(b * SEQ + n0 + row0 + 8)) * DIM + h * HDIM + d;
        out[base0]     = oacc[nt][0] * inv0;
        out[base0 + 1] = oacc[nt][1] * inv0;
        out[base1]     = oacc[nt][2] * inv1;
        out[base1 + 1] = oacc[nt][3] * inv1;
    }
}

// ============================ launch ============================
extern "C" void kernel_launch(void* const* d_in, const int* in_sizes, int n_in,
                              void* d_out, int out_size)
{
    const float* x      = (const float*)d_in[0];
    const float* ln1_g  = (const float*)d_in[1];
    const float* ln1_b  = (const float*)d_in[2];
    const float* ln2_g  = (const float*)d_in[3];
    const float* ln2_b  = (const float*)d_in[4];
    const float* qkv_w  = (const float*)d_in[5];
    const float* qkv_b  = (const float*)d_in[6];
    const float* proj_w = (const float*)d_in[7];
    const float* proj_b = (const float*)d_in[8];
    const float* fc1_w  = (const float*)d_in[9];
    const float* fc1_b  = (const float*)d_in[10];
    const float* fc2_w  = (const float*)d_in[11];
    const float* fc2_b  = (const float*)d_in[12];
    const float* attn_a = (const float*)d_in[13];
    const float* attn_b = (const float*)d_in[14];
    const float* attn_c = (const float*)d_in[15];
    const float* gelu_a = (const float*)d_in[16];
    const float* gelu_b = (const float*)d_in[17];
    const float* gelu_c = (const float*)d_in[18];
    float* out = (float*)d_out;

    void *p_h, *p_q, *p_k, *p_v, *p_ao, *p_x1, *p_u;
    cudaGetSymbolAddress(&p_h,  g_h);
    cudaGetSymbolAddress(&p_q,  g_q);
    cudaGetSymbolAddress(&p_k,  g_k);
    cudaGetSymbolAddress(&p_v,  g_v);
    cudaGetSymbolAddress(&p_ao, g_attnout);
    cudaGetSymbolAddress(&p_x1, g_x1);
    cudaGetSymbolAddress(&p_u,  g_u);
    float* h_  = (float*)p_h;
    float* q_  = (float*)p_q;
    float* k_  = (float*)p_k;
    float* v_  = (float*)p_v;
    float* ao_ = (float*)p_ao;
    float* x1_ = (float*)p_x1;
    float* u_  = (float*)p_u;

    // 1. LN1
    ln_kernel<<<TOK, 256>>>(x, ln1_g, ln1_b, h_);
    // 2. QKV GEMM (tensor cores) with head-major scatter
    mma_gemm<1><<<dim3(3 * DIM / 128, TOK / 128), 256>>>(
        h_, qkv_w, qkv_b, nullptr, nullptr, TOK, 3 * DIM, DIM,
        q_, k_, v_, nullptr, nullptr, nullptr);
    // 3. polynomial attention (tensor cores, single pass)
    attn_mma<<<dim3(SEQ / 64, BH), 256>>>(q_, k_, v_, ao_,
                                          attn_a, attn_b, attn_c);
    // 4. proj GEMM + residual -> x1
    mma_gemm<2><<<dim3(DIM / 128, TOK / 128), 256>>>(
        ao_, proj_w, proj_b, x, x1_, TOK, DIM, DIM,
        nullptr, nullptr, nullptr, nullptr, nullptr, nullptr);
    // 5. LN2
    ln_kernel<<<TOK, 256>>>(x1_, ln2_g, ln2_b, h_);
    // 6. FC1 GEMM + PolyGELU
    mma_gemm<3><<<dim3(HID / 128, TOK / 128), 256>>>(
        h_, fc1_w, fc1_b, nullptr, u_, TOK, HID, DIM,
        nullptr, nullptr, nullptr, gelu_a, gelu_b, gelu_c);
    // 7. FC2 GEMM + residual -> out
    mma_gemm<2><<<dim3(DIM / 128, TOK / 128), 256>>>(
        u_, fc2_w, fc2_b, x1_, out, TOK, DIM, HID,
        nullptr, nullptr, nullptr, nullptr, nullptr, nullptr);
}

// round 3
// speedup vs baseline: 3.3303x; 1.2275x over previous
#include <cuda_runtime.h>
#include <cuda_bf16.h>

#define TOK   8192
#define SEQ   2048
#define BATCH 4
#define DIM   768
#define NHEAD 12
#define HDIM  64
#define BH    (BATCH*NHEAD)
#define HID   3072
#define QKSCALE 0.125f
#define LN_EPS 1e-5f

__device__ float g_h[TOK * DIM];
__device__ float g_q[BH * SEQ * HDIM];
__device__ float g_k[BH * SEQ * HDIM];
__device__ float g_v[BH * SEQ * HDIM];
__device__ float g_attnout[TOK * DIM];
__device__ float g_x1[TOK * DIM];
__device__ float g_u[TOK * HID];

__device__ __forceinline__ unsigned f2tf(float x) {
    unsigned r;
    asm("cvt.rna.tf32.f32 %0, %1;" : "=r"(r) : "f"(x));
    return r;
}

__device__ __forceinline__ void mma_tf32(float& d0, float& d1, float& d2, float& d3,
                                         unsigned a0, unsigned a1, unsigned a2, unsigned a3,
                                         unsigned b0, unsigned b1)
{
    asm volatile(
        "mma.sync.aligned.m16n8k8.row.col.f32.tf32.tf32.f32 "
        "{%0,%1,%2,%3},{%4,%5,%6,%7},{%8,%9},{%0,%1,%2,%3};"
        : "+f"(d0), "+f"(d1), "+f"(d2), "+f"(d3)
        : "r"(a0), "r"(a1), "r"(a2), "r"(a3), "r"(b0), "r"(b1));
}

__device__ __forceinline__ void ldsm4(unsigned& r0, unsigned& r1, unsigned& r2, unsigned& r3,
                                      unsigned addr)
{
    asm volatile("ldmatrix.sync.aligned.m8n8.x4.shared.b16 {%0,%1,%2,%3}, [%4];"
        : "=r"(r0), "=r"(r1), "=r"(r2), "=r"(r3) : "r"(addr));
}

// ============================ LayerNorm ============================
__global__ __launch_bounds__(256) void ln_kernel(
    const float* __restrict__ x, const float* __restrict__ gamma,
    const float* __restrict__ beta, float* __restrict__ out)
{
    int row = blockIdx.x;
    const float* xr = x + (size_t)row * DIM;
    float s = 0.f, s2 = 0.f;
    for (int i = threadIdx.x; i < DIM; i += 256) {
        float v = xr[i]; s += v; s2 += v * v;
    }
    #pragma unroll
    for (int o = 16; o; o >>= 1) {
        s  += __shfl_xor_sync(0xffffffffu, s,  o);
        s2 += __shfl_xor_sync(0xffffffffu, s2, o);
    }
    __shared__ float rs[8], rs2[8];
    int lane = threadIdx.x & 31, wid = threadIdx.x >> 5;
    if (lane == 0) { rs[wid] = s; rs2[wid] = s2; }
    __syncthreads();
    float ts = 0.f, ts2 = 0.f;
    #pragma unroll
    for (int i = 0; i < 8; i++) { ts += rs[i]; ts2 += rs2[i]; }
    float mean = ts * (1.0f / DIM);
    float var  = ts2 * (1.0f / DIM) - mean * mean;
    float inv  = rsqrtf(var + LN_EPS);
    float* orow = out + (size_t)row * DIM;
    for (int i = threadIdx.x; i < DIM; i += 256)
        orow[i] = (xr[i] - mean) * inv * gamma[i] + beta[i];
}

// ============================ TF32 GEMM, double-buffered ============================
template <int EPI>
__global__ __launch_bounds__(256, 2) void mma_gemm(
    const float* __restrict__ A, const float* __restrict__ W,
    const float* __restrict__ bias, const float* __restrict__ res,
    float* __restrict__ C, int M, int N, int K,
    float* __restrict__ qo, float* __restrict__ ko, float* __restrict__ vo,
    const float* __restrict__ c0, const float* __restrict__ c1,
    const float* __restrict__ c2)
{
    __shared__ unsigned As[2][128 * 20];
    __shared__ unsigned Bs[2][16 * 136];

    const int tid  = threadIdx.x;
    const int lane = tid & 31;
    const int w    = tid >> 5;
    const int wm   = w >> 2;
    const int wn   = w & 3;
    const int bx = blockIdx.x, by = blockIdx.y;

    const int arow = tid >> 2, ac4 = tid & 3;
    const int brow = tid >> 5, bc4 = tid & 31;

    const float* Aptr = A + (size_t)(by * 128 + arow) * K + ac4 * 4;
    const float* Bptr = W + (size_t)brow * N + bx * 128 + bc4 * 4;

    float acc[4][4][4];
    #pragma unroll
    for (int i = 0; i < 4; i++)
        #pragma unroll
        for (int j = 0; j < 4; j++)
            #pragma unroll
            for (int r = 0; r < 4; r++) acc[i][j][r] = 0.f;

    const int nt = K >> 4;
    float4 ra0, ra1, rb0, rb1;

    // tile t global load
    {
        ra0 = *(const float4*)(Aptr);
        ra1 = *(const float4*)(Aptr + (size_t)64 * K);
        rb0 = *(const float4*)(Bptr);
        rb1 = *(const float4*)(Bptr + (size_t)8 * N);
    }
    // store tile0 -> stage0
    {
        unsigned* pa  = As[0] + arow * 20 + ac4 * 4;
        pa[0] = f2tf(ra0.x); pa[1] = f2tf(ra0.y); pa[2] = f2tf(ra0.z); pa[3] = f2tf(ra0.w);
        unsigned* pa2 = As[0] + (arow + 64) * 20 + ac4 * 4;
        pa2[0] = f2tf(ra1.x); pa2[1] = f2tf(ra1.y); pa2[2] = f2tf(ra1.z); pa2[3] = f2tf(ra1.w);
        unsigned* pb  = Bs[0] + brow * 136 + bc4 * 4;
        pb[0] = f2tf(rb0.x); pb[1] = f2tf(rb0.y); pb[2] = f2tf(rb0.z); pb[3] = f2tf(rb0.w);
        unsigned* pb2 = Bs[0] + (brow + 8) * 136 + bc4 * 4;
        pb2[0] = f2tf(rb1.x); pb2[1] = f2tf(rb1.y); pb2[2] = f2tf(rb1.z); pb2[3] = f2tf(rb1.w);
    }
    if (nt > 1) {
        const float* ap = Aptr + 16;
        const float* bp = Bptr + (size_t)16 * N;
        ra0 = *(const float4*)(ap);
        ra1 = *(const float4*)(ap + (size_t)64 * K);
        rb0 = *(const float4*)(bp);
        rb1 = *(const float4*)(bp + (size_t)8 * N);
    }
    __syncthreads();

    const unsigned a_laneoff = (((lane & 7) + ((lane >> 3) & 1) * 8) * 20 + (lane >> 4) * 4) * 4;

    for (int t = 0; t < nt; t++) {
        int s = t & 1;
        if (t + 1 < nt) {
            unsigned* pa  = As[s ^ 1] + arow * 20 + ac4 * 4;
            pa[0] = f2tf(ra0.x); pa[1] = f2tf(ra0.y); pa[2] = f2tf(ra0.z); pa[3] = f2tf(ra0.w);
            unsigned* pa2 = As[s ^ 1] + (arow + 64) * 20 + ac4 * 4;
            pa2[0] = f2tf(ra1.x); pa2[1] = f2tf(ra1.y); pa2[2] = f2tf(ra1.z); pa2[3] = f2tf(ra1.w);
            unsigned* pb  = Bs[s ^ 1] + brow * 136 + bc4 * 4;
            pb[0] = f2tf(rb0.x); pb[1] = f2tf(rb0.y); pb[2] = f2tf(rb0.z); pb[3] = f2tf(rb0.w);
            unsigned* pb2 = Bs[s ^ 1] + (brow + 8) * 136 + bc4 * 4;
            pb2[0] = f2tf(rb1.x); pb2[1] = f2tf(rb1.y); pb2[2] = f2tf(rb1.z); pb2[3] = f2tf(rb1.w);
        }
        if (t + 2 < nt) {
            const float* ap = Aptr + (t + 2) * 16;
            const float* bp = Bptr + (size_t)(t + 2) * 16 * N;
            ra0 = *(const float4*)(ap);
            ra1 = *(const float4*)(ap + (size_t)64 * K);
            rb0 = *(const float4*)(bp);
            rb1 = *(const float4*)(bp + (size_t)8 * N);
        }
        unsigned sA = (unsigned)__cvta_generic_to_shared(As[s]);
        const unsigned* BsS = Bs[s];
        #pragma unroll
        for (int kk = 0; kk < 16; kk += 8) {
            unsigned af[4][4], bf[4][2];
            #pragma unroll
            for (int mt = 0; mt < 4; mt++) {
                unsigned addr = sA + ((wm * 64 + mt * 16) * 20 + kk) * 4 + a_laneoff;
                ldsm4(af[mt][0], af[mt][1], af[mt][2], af[mt][3], addr);
            }
            #pragma unroll
            for (int ntt = 0; ntt < 4; ntt++) {
                int col = wn * 32 + ntt * 8 + (lane >> 2);
                bf[ntt][0] = BsS[(kk + (lane & 3)) * 136 + col];
                bf[ntt][1] = BsS[(kk + (lane & 3) + 4) * 136 + col];
            }
            #pragma unroll
            for (int mt = 0; mt < 4; mt++)
                #pragma unroll
                for (int ntt = 0; ntt < 4; ntt++)
                    mma_tf32(acc[mt][ntt][0], acc[mt][ntt][1], acc[mt][ntt][2], acc[mt][ntt][3],
                             af[mt][0], af[mt][1], af[mt][2], af[mt][3],
                             bf[ntt][0], bf[ntt][1]);
        }
        __syncthreads();
    }

    float ga = 0.f, gb = 0.f, gc = 0.f;
    if (EPI == 3) { ga = *c0; gb = *c1; gc = *c2; }

    #pragma unroll
    for (int mt = 0; mt < 4; mt++) {
        #pragma unroll
        for (int ntt = 0; ntt < 4; ntt++) {
            int r0  = by * 128 + wm * 64 + mt * 16 + (lane >> 2);
            int cc0 = bx * 128 + wn * 32 + ntt * 8 + 2 * (lane & 3);
            #pragma unroll
            for (int half = 0; half < 2; half++) {
                int r = r0 + half * 8;
                float v0 = acc[mt][ntt][half * 2 + 0] + bias[cc0];
                float v1 = acc[mt][ntt][half * 2 + 1] + bias[cc0 + 1];
                if (EPI == 1) {
                    int which = cc0 / DIM;
                    int jj = cc0 - which * DIM;
                    int h = jj >> 6, d = jj & 63;
                    int b = r >> 11, n = r & 2047;
                    float* dst = (which == 0) ? qo : (which == 1) ? ko : vo;
                    size_t base = (((size_t)(b * NHEAD + h) * SEQ) + n) * HDIM + d;
                    dst[base] = v0; dst[base + 1] = v1;
                } else if (EPI == 2) {
                    size_t base = (size_t)r * N + cc0;
                    C[base]     = v0 + res[base];
                    C[base + 1] = v1 + res[base + 1];
                } else if (EPI == 3) {
                    size_t base = (size_t)r * N + cc0;
                    C[base]     = fmaf(v0, fmaf(ga, v0, gb), gc);
                    C[base + 1] = fmaf(v1, fmaf(ga, v1, gb), gc);
                } else {
                    size_t base = (size_t)r * N + cc0;
                    C[base] = v0; C[base + 1] = v1;
                }
            }
        }
    }
}

// ============================ Polynomial attention, pipelined ============================
// dyn smem: Ks[64][68], Vs[64][72], Ss[64][68]
#define ATTN_SMEM ((64*68 + 64*72 + 64*68) * 4)

__global__ __launch_bounds__(256, 2) void attn_mma(
    const float* __restrict__ Q, const float* __restrict__ Kg,
    const float* __restrict__ Vg, float* __restrict__ out,
    const float* __restrict__ pa, const float* __restrict__ pb,
    const float* __restrict__ pc)
{
    extern __shared__ unsigned dsm[];
    unsigned* Ks = dsm;                 // [64][68]
    unsigned* Vs = dsm + 64 * 68;       // [64][72]
    unsigned* Ss = Vs + 64 * 72;        // [64][68]
    __shared__ float rsums[64];

    const int tid  = threadIdx.x;
    const int lane = tid & 31;
    const int w    = tid >> 5;
    const int mt   = w >> 1;
    const int nh   = w & 1;
    const int bh   = blockIdx.y;
    const int n0   = blockIdx.x * 64;

    const float* Qb = Q  + (size_t)bh * SEQ * HDIM;
    const float* Kb = Kg + (size_t)bh * SEQ * HDIM;
    const float* Vb = Vg + (size_t)bh * SEQ * HDIM;

    const float aa = *pa, bb = *pb, cc = *pc;

    if (tid < 64) rsums[tid] = 0.f;

    const int grow = tid >> 4;          // 0..15
    const int gc4  = tid & 15;

    // stage Q (scaled tf32) into Ss
    #pragma unroll
    for (int it = 0; it < 4; it++) {
        int r = it * 16 + grow;
        float4 v = *(const float4*)(Qb + (size_t)(n0 + r) * HDIM + gc4 * 4);
        unsigned* p = Ss + r * 68 + gc4 * 4;
        p[0] = f2tf(v.x * QKSCALE); p[1] = f2tf(v.y * QKSCALE);
        p[2] = f2tf(v.z * QKSCALE); p[3] = f2tf(v.w * QKSCALE);
    }

    float4 kr[4], vr[4];
    #pragma unroll
    for (int it = 0; it < 4; it++) {
        kr[it] = *(const float4*)(Kb + (size_t)(it * 16 + grow) * HDIM + gc4 * 4);
        vr[it] = *(const float4*)(Vb + (size_t)(it * 16 + grow) * HDIM + gc4 * 4);
    }
    __syncthreads();

    const unsigned sSs = (unsigned)__cvta_generic_to_shared(Ss);
    const unsigned sKs = (unsigned)__cvta_generic_to_shared(Ks);
    const unsigned a_laneoff = (((lane & 7) + ((lane >> 3) & 1) * 8) * 68 + (lane >> 4) * 4) * 4;
    const unsigned b_laneoff = (((lane & 7) + ((lane >> 4) & 1) * 8) * 68 + ((lane >> 3) & 1) * 4) * 4;

    // qf fragments from Ss
    unsigned qf[8][4];
    #pragma unroll
    for (int kk = 0; kk < 8; kk++) {
        unsigned addr = sSs + (mt * 16 * 68 + kk * 8) * 4 + a_laneoff;
        ldsm4(qf[kk][0], qf[kk][1], qf[kk][2], qf[kk][3], addr);
    }
    // store K0 -> Ks
    #pragma unroll
    for (int it = 0; it < 4; it++) {
        unsigned* p = Ks + (it * 16 + grow) * 68 + gc4 * 4;
        p[0] = f2tf(kr[it].x); p[1] = f2tf(kr[it].y);
        p[2] = f2tf(kr[it].z); p[3] = f2tf(kr[it].w);
    }
    // prefetch K1
    #pragma unroll
    for (int it = 0; it < 4; it++)
        kr[it] = *(const float4*)(Kb + (size_t)(64 + it * 16 + grow) * HDIM + gc4 * 4);
    __syncthreads();

    float oacc[4][4];
    #pragma unroll
    for (int ntt = 0; ntt < 4; ntt++)
        #pragma unroll
        for (int r = 0; r < 4; r++) oacc[ntt][r] = 0.f;
    float rs0 = 0.f, rs1 = 0.f;

    for (int i = 0; i < 32; i++) {
        // ---- S = Q K^T on Ks ----
        float sacc[4][4];
        #pragma unroll
        for (int ntt = 0; ntt < 4; ntt++)
            #pragma unroll
            for (int r = 0; r < 4; r++) sacc[ntt][r] = 0.f;

        #pragma unroll
        for (int kk = 0; kk < 8; kk++) {
            unsigned bf[4][2];
            #pragma unroll
            for (int p = 0; p < 2; p++) {
                unsigned addr = sKs + ((nh * 32 + p * 16) * 68 + kk * 8) * 4 + b_laneoff;
                ldsm4(bf[2 * p][0], bf[2 * p][1], bf[2 * p + 1][0], bf[2 * p + 1][1], addr);
            }
            #pragma unroll
            for (int ntt = 0; ntt < 4; ntt++)
                mma_tf32(sacc[ntt][0], sacc[ntt][1], sacc[ntt][2], sacc[ntt][3],
                         qf[kk][0], qf[kk][1], qf[kk][2], qf[kk][3],
                         bf[ntt][0], bf[ntt][1]);
        }

        // f(S) + rowsum
        #pragma unroll
        for (int ntt = 0; ntt < 4; ntt++) {
            #pragma unroll
            for (int r = 0; r < 4; r++) {
                float t = sacc[ntt][r];
                t = fmaf(t, fmaf(aa, t, bb), cc);
                t = fmaxf(t, 1e-6f);
                sacc[ntt][r] = t;
                if (r < 2) rs0 += t; else rs1 += t;
            }
        }

        __syncthreads();   // sync1: prior O-mma reads (Ss,Vs) and this S-mma reads (Ks) done

        // store f(S) -> Ss
        #pragma unroll
        for (int ntt = 0; ntt < 4; ntt++) {
            int row = mt * 16 + (lane >> 2);
            int col = nh * 32 + ntt * 8 + 2 * (lane & 3);
            uint2 u0 = make_uint2(f2tf(sacc[ntt][0]), f2tf(sacc[ntt][1]));
            uint2 u1 = make_uint2(f2tf(sacc[ntt][2]), f2tf(sacc[ntt][3]));
            *(uint2*)&Ss[row * 68 + col]       = u0;
            *(uint2*)&Ss[(row + 8) * 68 + col] = u1;
        }
        // store V_i -> Vs (straight, ld 72)
        #pragma unroll
        for (int it = 0; it < 4; it++) {
            uint4 u = make_uint4(f2tf(vr[it].x), f2tf(vr[it].y), f2tf(vr[it].z), f2tf(vr[it].w));
            *(uint4*)(Vs + (it * 16 + grow) * 72 + gc4 * 4) = u;
        }
        // store K_{i+1} -> Ks
        #pragma unroll
        for (int it = 0; it < 4; it++) {
            unsigned* p = Ks + (it * 16 + grow) * 68 + gc4 * 4;
            p[0] = f2tf(kr[it].x); p[1] = f2tf(kr[it].y);
            p[2] = f2tf(kr[it].z); p[3] = f2tf(kr[it].w);
        }
        // prefetch V_{i+1}, K_{i+2}
        {
            int vi = (i + 1 < 32) ? (i + 1) : 31;
            int ki = (i + 2 < 32) ? (i + 2) : 31;
            #pragma unroll
            for (int it = 0; it < 4; it++) {
                vr[it] = *(const float4*)(Vb + (size_t)(vi * 64 + it * 16 + grow) * HDIM + gc4 * 4);
                kr[it] = *(const float4*)(Kb + (size_t)(ki * 64 + it * 16 + grow) * HDIM + gc4 * 4);
            }
        }
        __syncthreads();   // sync2

        // ---- O += f(S) @ V ----
        #pragma unroll
        for (int kk = 0; kk < 8; kk++) {
            unsigned af[4];
            unsigned addr = sSs + (mt * 16 * 68 + kk * 8) * 4 + a_laneoff;
            ldsm4(af[0], af[1], af[2], af[3], addr);
            unsigned bfv[4][2];
            #pragma unroll
            for (int ntt = 0; ntt < 4; ntt++) {
                int dcol = nh * 32 + ntt * 8 + (lane >> 2);
                bfv[ntt][0] = Vs[(kk * 8 + (lane & 3)) * 72 + dcol];
                bfv[ntt][1] = Vs[(kk * 8 + (lane & 3) + 4) * 72 + dcol];
            }
            #pragma unroll
            for (int ntt = 0; ntt < 4; ntt++)
                mma_tf32(oacc[ntt][0], oacc[ntt][1], oacc[ntt][2], oacc[ntt][3],
                         af[0], af[1], af[2], af[3],
                         bfv[ntt][0], bfv[ntt][1]);
        }
    }

    // rowsum reduce (lanes l, l^1, l^2 share row)
    rs0 += __shfl_xor_sync(0xffffffffu, rs0, 1);
    rs0 += __shfl_xor_sync(0xffffffffu, rs0, 2);
    rs1 += __shfl_xor_sync(0xffffffffu, rs1, 1);
    rs1 += __shfl_xor_sync(0xffffffffu, rs1, 2);
    if ((lane & 3) == 0) {
        atomicAdd(&rsums[mt * 16 + (lane >> 2)], rs0);
        atomicAdd(&rsums[mt * 16 + (lane >> 2) + 8], rs1);
    }
    __syncthreads();

    int b = bh / NHEAD, h = bh % NHEAD;
    int row0 = mt * 16 + (lane >> 2);
    float inv0 = 1.0f / (rsums[row0] + 1e-8f);
    float inv1 = 1.0f / (rsums[row0 + 8] + 1e-8f);
    #pragma unroll
    for (int ntt = 0; ntt < 4; ntt++) {
        int d = nh * 32 + ntt * 8 + 2 * (lane & 3);
        size_t base0 = ((size_t)(b * SEQ + n0 + row0)) * DIM + h * HDIM + d;
        size_t base1 = ((size_t)(b * SEQ + n0 + row0 + 8)) * DIM + h * HDIM + d;
        out[base0]     = oacc[ntt][0] * inv0;
        out[base0 + 1] = oacc[ntt][1] * inv0;
        out[base1]     = oacc[ntt][2] * inv1;
        out[base1 + 1] = oacc[ntt][3] * inv1;
    }
}

// ============================ launch ============================
extern "C" void kernel_launch(void* const* d_in, const int* in_sizes, int n_in,
                              void* d_out, int out_size)
{
    const float* x      = (const float*)d_in[0];
    const float* ln1_g  = (const float*)d_in[1];
    const float* ln1_b  = (const float*)d_in[2];
    const float* ln2_g  = (const float*)d_in[3];
    const float* ln2_b  = (const float*)d_in[4];
    const float* qkv_w  = (const float*)d_in[5];
    const float* qkv_b  = (const float*)d_in[6];
    const float* proj_w = (const float*)d_in[7];
    const float* proj_b = (const float*)d_in[8];
    const float* fc1_w  = (const float*)d_in[9];
    const float* fc1_b  = (const float*)d_in[10];
    const float* fc2_w  = (const float*)d_in[11];
    const float* fc2_b  = (const float*)d_in[12];
    const float* attn_a = (const float*)d_in[13];
    const float* attn_b = (const float*)d_in[14];
    const float* attn_c = (const float*)d_in[15];
    const float* gelu_a = (const float*)d_in[16];
    const float* gelu_b = (const float*)d_in[17];
    const float* gelu_c = (const float*)d_in[18];
    float* out = (float*)d_out;

    void *p_h, *p_q, *p_k, *p_v, *p_ao, *p_x1, *p_u;
    cudaGetSymbolAddress(&p_h,  g_h);
    cudaGetSymbolAddress(&p_q,  g_q);
    cudaGetSymbolAddress(&p_k,  g_k);
    cudaGetSymbolAddress(&p_v,  g_v);
    cudaGetSymbolAddress(&p_ao, g_attnout);
    cudaGetSymbolAddress(&p_x1, g_x1);
    cudaGetSymbolAddress(&p_u,  g_u);
    float* h_  = (float*)p_h;
    float* q_  = (float*)p_q;
    float* k_  = (float*)p_k;
    float* v_  = (float*)p_v;
    float* ao_ = (float*)p_ao;
    float* x1_ = (float*)p_x1;
    float* u_  = (float*)p_u;

    static int attr_set = 0;
    if (!attr_set) {
        cudaFuncSetAttribute(attn_mma, cudaFuncAttributeMaxDynamicSharedMemorySize, ATTN_SMEM);
        attr_set = 1;
    }

    ln_kernel<<<TOK, 256>>>(x, ln1_g, ln1_b, h_);
    mma_gemm<1><<<dim3(3 * DIM / 128, TOK / 128), 256>>>(
        h_, qkv_w, qkv_b, nullptr, nullptr, TOK, 3 * DIM, DIM,
        q_, k_, v_, nullptr, nullptr, nullptr);
    attn_mma<<<dim3(SEQ / 64, BH), 256, ATTN_SMEM>>>(q_, k_, v_, ao_,
                                                     attn_a, attn_b, attn_c);
    mma_gemm<2><<<dim3(DIM / 128, TOK / 128), 256>>>(
        ao_, proj_w, proj_b, x, x1_, TOK, DIM, DIM,
        nullptr, nullptr, nullptr, nullptr, nullptr, nullptr);
    ln_kernel<<<TOK, 256>>>(x1_, ln2_g, ln2_b, h_);
    mma_gemm<3><<<dim3(HID / 128, TOK / 128), 256>>>(
        h_, fc1_w, fc1_b, nullptr, u_, TOK, HID, DIM,
        nullptr, nullptr, nullptr, gelu_a, gelu_b, gelu_c);
    mma_gemm<2><<<dim3(DIM / 128, TOK / 128), 256>>>(
        u_, fc2_w, fc2_b, x1_, out, TOK, DIM, HID,
        nullptr, nullptr, nullptr, nullptr, nullptr, nullptr);
}

// round 4
// speedup vs baseline: 3.6251x; 1.0885x over previous
#include <cuda_runtime.h>
#include <cuda_bf16.h>

#define TOK   8192
#define SEQ   2048
#define BATCH 4
#define DIM   768
#define NHEAD 12
#define HDIM  64
#define BH    (BATCH*NHEAD)
#define HID   3072
#define QKSCALE 0.125f
#define LN_EPS 1e-5f

__device__ float g_h[TOK * DIM];
__device__ float g_q[BH * SEQ * HDIM];
__device__ float g_k[BH * SEQ * HDIM];
__device__ float g_v[BH * SEQ * HDIM];
__device__ float g_attnout[TOK * DIM];
__device__ float g_x1[TOK * DIM];
__device__ float g_u[TOK * HID];

__device__ __forceinline__ void mma_tf32(float& d0, float& d1, float& d2, float& d3,
                                         unsigned a0, unsigned a1, unsigned a2, unsigned a3,
                                         unsigned b0, unsigned b1)
{
    asm volatile(
        "mma.sync.aligned.m16n8k8.row.col.f32.tf32.tf32.f32 "
        "{%0,%1,%2,%3},{%4,%5,%6,%7},{%8,%9},{%0,%1,%2,%3};"
        : "+f"(d0), "+f"(d1), "+f"(d2), "+f"(d3)
        : "r"(a0), "r"(a1), "r"(a2), "r"(a3), "r"(b0), "r"(b1));
}

__device__ __forceinline__ void ldsm4(unsigned& r0, unsigned& r1, unsigned& r2, unsigned& r3,
                                      unsigned addr)
{
    asm volatile("ldmatrix.sync.aligned.m8n8.x4.shared.b16 {%0,%1,%2,%3}, [%4];"
        : "=r"(r0), "=r"(r1), "=r"(r2), "=r"(r3) : "r"(addr));
}

__device__ __forceinline__ void cp16(unsigned saddr, const void* gptr) {
    asm volatile("cp.async.cg.shared.global [%0], [%1], 16;" :: "r"(saddr), "l"(gptr));
}
#define CP_COMMIT() asm volatile("cp.async.commit_group;")
#define CP_WAIT(n)  asm volatile("cp.async.wait_group %0;" :: "n"(n))

// ============================ LayerNorm (vectorized) ============================
__global__ __launch_bounds__(192) void ln_kernel(
    const float* __restrict__ x, const float* __restrict__ gamma,
    const float* __restrict__ beta, float* __restrict__ out)
{
    int row = blockIdx.x;
    int tid = threadIdx.x;
    const float* xr = x + (size_t)row * DIM;
    float4 v = *(const float4*)(xr + tid * 4);
    float s  = v.x + v.y + v.z + v.w;
    float s2 = v.x * v.x + v.y * v.y + v.z * v.z + v.w * v.w;
    #pragma unroll
    for (int o = 16; o; o >>= 1) {
        s  += __shfl_xor_sync(0xffffffffu, s,  o);
        s2 += __shfl_xor_sync(0xffffffffu, s2, o);
    }
    __shared__ float rs[6], rs2[6];
    int lane = tid & 31, wid = tid >> 5;
    if (lane == 0) { rs[wid] = s; rs2[wid] = s2; }
    __syncthreads();
    float ts = 0.f, ts2 = 0.f;
    #pragma unroll
    for (int i = 0; i < 6; i++) { ts += rs[i]; ts2 += rs2[i]; }
    float mean = ts * (1.0f / DIM);
    float var  = ts2 * (1.0f / DIM) - mean * mean;
    float inv  = rsqrtf(var + LN_EPS);
    float4 g = *(const float4*)(gamma + tid * 4);
    float4 b = *(const float4*)(beta + tid * 4);
    float4 o;
    o.x = (v.x - mean) * inv * g.x + b.x;
    o.y = (v.y - mean) * inv * g.y + b.y;
    o.z = (v.z - mean) * inv * g.z + b.z;
    o.w = (v.w - mean) * inv * g.w + b.w;
    *(float4*)(out + (size_t)row * DIM + tid * 4) = o;
}

// ============================ TF32 GEMM, 3-stage cp.async ============================
#define AS_W 20
#define BS_W 136
#define AS_STAGE (128 * AS_W)
#define BS_STAGE (16 * BS_W)
#define STAGE_W  (AS_STAGE + BS_STAGE)
#define GEMM_SMEM (3 * STAGE_W * 4)

template <int EPI>
__global__ __launch_bounds__(256, 2) void mma_gemm(
    const float* __restrict__ A, const float* __restrict__ W,
    const float* __restrict__ bias, const float* __restrict__ res,
    float* __restrict__ C, int M, int N, int K,
    float* __restrict__ qo, float* __restrict__ ko, float* __restrict__ vo,
    const float* __restrict__ c0, const float* __restrict__ c1,
    const float* __restrict__ c2)
{
    extern __shared__ unsigned smem[];

    const int tid  = threadIdx.x;
    const int lane = tid & 31;
    const int w    = tid >> 5;
    const int wm   = w >> 2;
    const int wn   = w & 3;
    const int bx = blockIdx.x, by = blockIdx.y;

    const int arow = tid >> 2, ac4 = tid & 3;
    const int brow = tid >> 5, bc4 = tid & 31;

    const float* Ag = A + (size_t)(by * 128 + arow) * K + ac4 * 4;
    const float* Bg = W + (size_t)brow * N + bx * 128 + bc4 * 4;

    const unsigned sbase = (unsigned)__cvta_generic_to_shared(smem);
    const unsigned aoff0 = (arow * AS_W + ac4 * 4) * 4;
    const unsigned aoff1 = ((arow + 64) * AS_W + ac4 * 4) * 4;
    const unsigned boff0 = (AS_STAGE + brow * BS_W + bc4 * 4) * 4;
    const unsigned boff1 = (AS_STAGE + (brow + 8) * BS_W + bc4 * 4) * 4;

    const int nt = K >> 4;

    // prologue: stages 0,1
    #pragma unroll
    for (int t = 0; t < 2; t++) {
        unsigned sb = sbase + t * STAGE_W * 4;
        cp16(sb + aoff0, Ag + t * 16);
        cp16(sb + aoff1, Ag + (size_t)64 * K + t * 16);
        cp16(sb + boff0, Bg + (size_t)(t * 16) * N);
        cp16(sb + boff1, Bg + (size_t)(t * 16 + 8) * N);
        CP_COMMIT();
    }

    float acc[4][4][4];
    #pragma unroll
    for (int i = 0; i < 4; i++)
        #pragma unroll
        for (int j = 0; j < 4; j++)
            #pragma unroll
            for (int r = 0; r < 4; r++) acc[i][j][r] = 0.f;

    const unsigned a_laneoff = (((lane & 7) + ((lane >> 3) & 1) * 8) * AS_W + (lane >> 4) * 4) * 4;

    int stage = 0;
    for (int t = 0; t < nt; t++) {
        CP_WAIT(1);
        __syncthreads();
        // prefetch t+2
        if (t + 2 < nt) {
            int s2 = stage + 2; if (s2 >= 3) s2 -= 3;
            unsigned sb = sbase + s2 * STAGE_W * 4;
            int tt = t + 2;
            cp16(sb + aoff0, Ag + tt * 16);
            cp16(sb + aoff1, Ag + (size_t)64 * K + tt * 16);
            cp16(sb + boff0, Bg + (size_t)(tt * 16) * N);
            cp16(sb + boff1, Bg + (size_t)(tt * 16 + 8) * N);
        }
        CP_COMMIT();

        unsigned sA = sbase + stage * STAGE_W * 4;
        const unsigned* BsS = smem + stage * STAGE_W + AS_STAGE;
        #pragma unroll
        for (int kk = 0; kk < 16; kk += 8) {
            unsigned af[4][4], bf[4][2];
            #pragma unroll
            for (int mt = 0; mt < 4; mt++) {
                unsigned addr = sA + ((wm * 64 + mt * 16) * AS_W + kk) * 4 + a_laneoff;
                ldsm4(af[mt][0], af[mt][1], af[mt][2], af[mt][3], addr);
            }
            #pragma unroll
            for (int ntt = 0; ntt < 4; ntt++) {
                int col = wn * 32 + ntt * 8 + (lane >> 2);
                bf[ntt][0] = BsS[(kk + (lane & 3)) * BS_W + col];
                bf[ntt][1] = BsS[(kk + (lane & 3) + 4) * BS_W + col];
            }
            #pragma unroll
            for (int mt = 0; mt < 4; mt++)
                #pragma unroll
                for (int ntt = 0; ntt < 4; ntt++)
                    mma_tf32(acc[mt][ntt][0], acc[mt][ntt][1], acc[mt][ntt][2], acc[mt][ntt][3],
                             af[mt][0], af[mt][1], af[mt][2], af[mt][3],
                             bf[ntt][0], bf[ntt][1]);
        }
        __syncthreads();
        stage++; if (stage == 3) stage = 0;
    }

    float ga = 0.f, gb = 0.f, gc = 0.f;
    if (EPI == 3) { ga = *c0; gb = *c1; gc = *c2; }

    #pragma unroll
    for (int mt = 0; mt < 4; mt++) {
        #pragma unroll
        for (int ntt = 0; ntt < 4; ntt++) {
            int r0  = by * 128 + wm * 64 + mt * 16 + (lane >> 2);
            int cc0 = bx * 128 + wn * 32 + ntt * 8 + 2 * (lane & 3);
            #pragma unroll
            for (int half = 0; half < 2; half++) {
                int r = r0 + half * 8;
                float v0 = acc[mt][ntt][half * 2 + 0] + bias[cc0];
                float v1 = acc[mt][ntt][half * 2 + 1] + bias[cc0 + 1];
                if (EPI == 1) {
                    int which = cc0 / DIM;
                    int jj = cc0 - which * DIM;
                    int h = jj >> 6, d = jj & 63;
                    int b = r >> 11, n = r & 2047;
                    float* dst = (which == 0) ? qo : (which == 1) ? ko : vo;
                    if (which == 0) { v0 *= QKSCALE; v1 *= QKSCALE; }  // fold attn scale into Q
                    size_t base = (((size_t)(b * NHEAD + h) * SEQ) + n) * HDIM + d;
                    dst[base] = v0; dst[base + 1] = v1;
                } else if (EPI == 2) {
                    size_t base = (size_t)r * N + cc0;
                    C[base]     = v0 + res[base];
                    C[base + 1] = v1 + res[base + 1];
                } else if (EPI == 3) {
                    size_t base = (size_t)r * N + cc0;
                    C[base]     = fmaf(v0, fmaf(ga, v0, gb), gc);
                    C[base + 1] = fmaf(v1, fmaf(ga, v1, gb), gc);
                } else {
                    size_t base = (size_t)r * N + cc0;
                    C[base] = v0; C[base + 1] = v1;
                }
            }
        }
    }
}

// ============================ Polynomial attention, cp.async double-buffered ============================
// dyn smem: Ks[2][64*68], Vs[2][64*72], Ss[64*68]
#define KS_W 68
#define VS_W 72
#define KS_T (64 * KS_W)
#define VS_T (64 * VS_W)
#define ATTN_SMEM ((2 * KS_T + 2 * VS_T + 64 * 68) * 4)

__global__ __launch_bounds__(256, 2) void attn_mma(
    const float* __restrict__ Q, const float* __restrict__ Kg,
    const float* __restrict__ Vg, float* __restrict__ out,
    const float* __restrict__ pa, const float* __restrict__ pb,
    const float* __restrict__ pc)
{
    extern __shared__ unsigned dsm[];
    unsigned* Ks = dsm;                       // 2 bufs [64][68]
    unsigned* Vs = dsm + 2 * KS_T;            // 2 bufs [64][72]
    unsigned* Ss = dsm + 2 * KS_T + 2 * VS_T; // [64][68]
    __shared__ float rsums[64];

    const int tid  = threadIdx.x;
    const int lane = tid & 31;
    const int w    = tid >> 5;
    const int mt   = w >> 1;
    const int nh   = w & 1;
    const int bh   = blockIdx.y;
    const int n0   = blockIdx.x * 64;

    const float* Qb = Q  + (size_t)bh * SEQ * HDIM;
    const float* Kb = Kg + (size_t)bh * SEQ * HDIM;
    const float* Vb = Vg + (size_t)bh * SEQ * HDIM;

    const float aa = *pa, bb = *pb, cc = *pc;

    if (tid < 64) rsums[tid] = 0.f;

    const int grow = tid >> 4;          // 0..15
    const int gc4  = tid & 15;

    const unsigned sKs = (unsigned)__cvta_generic_to_shared(Ks);
    const unsigned sVs = (unsigned)__cvta_generic_to_shared(Vs);
    const unsigned sSs = (unsigned)__cvta_generic_to_shared(Ss);

    // stage Q via cp.async into Ss
    #pragma unroll
    for (int it = 0; it < 4; it++) {
        int r = it * 16 + grow;
        cp16(sSs + (r * 68 + gc4 * 4) * 4, Qb + (size_t)(n0 + r) * HDIM + gc4 * 4);
    }
    CP_COMMIT();
    // prologue K/V tiles 0,1
    #pragma unroll
    for (int t = 0; t < 2; t++) {
        #pragma unroll
        for (int it = 0; it < 4; it++) {
            int r = it * 16 + grow;
            cp16(sKs + (t * KS_T + r * KS_W + gc4 * 4) * 4,
                 Kb + (size_t)(t * 64 + r) * HDIM + gc4 * 4);
            cp16(sVs + (t * VS_T + r * VS_W + gc4 * 4) * 4,
                 Vb + (size_t)(t * 64 + r) * HDIM + gc4 * 4);
        }
        CP_COMMIT();
    }
    CP_WAIT(2);   // Q landed
    __syncthreads();

    const unsigned a_laneoff = (((lane & 7) + ((lane >> 3) & 1) * 8) * 68 + (lane >> 4) * 4) * 4;
    const unsigned b_laneoff = (((lane & 7) + ((lane >> 4) & 1) * 8) * KS_W + ((lane >> 3) & 1) * 4) * 4;

    unsigned qf[8][4];
    #pragma unroll
    for (int kk = 0; kk < 8; kk++) {
        unsigned addr = sSs + (mt * 16 * 68 + kk * 8) * 4 + a_laneoff;
        ldsm4(qf[kk][0], qf[kk][1], qf[kk][2], qf[kk][3], addr);
    }

    float oacc[4][4];
    #pragma unroll
    for (int ntt = 0; ntt < 4; ntt++)
        #pragma unroll
        for (int r = 0; r < 4; r++) oacc[ntt][r] = 0.f;
    float rs0 = 0.f, rs1 = 0.f;

    for (int m = 0; m < 32; m++) {
        const int buf = m & 1;
        CP_WAIT(1);            // tile m resident
        __syncthreads();       // (a)

        // ---- S = Q K^T ----
        float sacc[4][4];
        #pragma unroll
        for (int ntt = 0; ntt < 4; ntt++)
            #pragma unroll
            for (int r = 0; r < 4; r++) sacc[ntt][r] = 0.f;

        unsigned kbase = sKs + buf * KS_T * 4;
        #pragma unroll
        for (int kk = 0; kk < 8; kk++) {
            unsigned bf[4][2];
            #pragma unroll
            for (int p = 0; p < 2; p++) {
                unsigned addr = kbase + ((nh * 32 + p * 16) * KS_W + kk * 8) * 4 + b_laneoff;
                ldsm4(bf[2 * p][0], bf[2 * p][1], bf[2 * p + 1][0], bf[2 * p + 1][1], addr);
            }
            #pragma unroll
            for (int ntt = 0; ntt < 4; ntt++)
                mma_tf32(sacc[ntt][0], sacc[ntt][1], sacc[ntt][2], sacc[ntt][3],
                         qf[kk][0], qf[kk][1], qf[kk][2], qf[kk][3],
                         bf[ntt][0], bf[ntt][1]);
        }

        // f(S) + rowsum
        #pragma unroll
        for (int ntt = 0; ntt < 4; ntt++) {
            #pragma unroll
            for (int r = 0; r < 4; r++) {
                float t = sacc[ntt][r];
                t = fmaf(t, fmaf(aa, t, bb), cc);
                t = fmaxf(t, 1e-6f);
                sacc[ntt][r] = t;
                if (r < 2) rs0 += t; else rs1 += t;
            }
        }

        // store f(S) -> Ss (raw fp32 bits; mma truncates)
        #pragma unroll
        for (int ntt = 0; ntt < 4; ntt++) {
            int row = mt * 16 + (lane >> 2);
            int col = nh * 32 + ntt * 8 + 2 * (lane & 3);
            uint2 u0 = make_uint2(__float_as_uint(sacc[ntt][0]), __float_as_uint(sacc[ntt][1]));
            uint2 u1 = make_uint2(__float_as_uint(sacc[ntt][2]), __float_as_uint(sacc[ntt][3]));
            *(uint2*)&Ss[row * 68 + col]       = u0;
            *(uint2*)&Ss[(row + 8) * 68 + col] = u1;
        }
        __syncthreads();       // (b): Ss ready, Ks reads done

        // ---- O += f(S) @ V ----
        const unsigned* Vbuf = Vs + buf * VS_T;
        #pragma unroll
        for (int kk = 0; kk < 8; kk++) {
            unsigned af[4];
            unsigned addr = sSs + (mt * 16 * 68 + kk * 8) * 4 + a_laneoff;
            ldsm4(af[0], af[1], af[2], af[3], addr);
            unsigned bfv[4][2];
            #pragma unroll
            for (int ntt = 0; ntt < 4; ntt++) {
                int dcol = nh * 32 + ntt * 8 + (lane >> 2);
                bfv[ntt][0] = Vbuf[(kk * 8 + (lane & 3)) * VS_W + dcol];
                bfv[ntt][1] = Vbuf[(kk * 8 + (lane & 3) + 4) * VS_W + dcol];
            }
            #pragma unroll
            for (int ntt = 0; ntt < 4; ntt++)
                mma_tf32(oacc[ntt][0], oacc[ntt][1], oacc[ntt][2], oacc[ntt][3],
                         af[0], af[1], af[2], af[3],
                         bfv[ntt][0], bfv[ntt][1]);
        }
        __syncthreads();       // (c): Vs reads done, safe to overwrite buf

        if (m + 2 < 32) {
            int tt = m + 2;
            #pragma unroll
            for (int it = 0; it < 4; it++) {
                int r = it * 16 + grow;
                cp16(sKs + (buf * KS_T + r * KS_W + gc4 * 4) * 4,
                     Kb + (size_t)(tt * 64 + r) * HDIM + gc4 * 4);
                cp16(sVs + (buf * VS_T + r * VS_W + gc4 * 4) * 4,
                     Vb + (size_t)(tt * 64 + r) * HDIM + gc4 * 4);
            }
        }
        CP_COMMIT();
    }

    // rowsum reduce
    rs0 += __shfl_xor_sync(0xffffffffu, rs0, 1);
    rs0 += __shfl_xor_sync(0xffffffffu, rs0, 2);
    rs1 += __shfl_xor_sync(0xffffffffu, rs1, 1);
    rs1 += __shfl_xor_sync(0xffffffffu, rs1, 2);
    if ((lane & 3) == 0) {
        atomicAdd(&rsums[mt * 16 + (lane >> 2)], rs0);
        atomicAdd(&rsums[mt * 16 + (lane >> 2) + 8], rs1);
    }
    __syncthreads();

    int b = bh / NHEAD, h = bh % NHEAD;
    int row0 = mt * 16 + (lane >> 2);
    float inv0 = 1.0f / (rsums[row0] + 1e-8f);
    float inv1 = 1.0f / (rsums[row0 + 8] + 1e-8f);
    #pragma unroll
    for (int ntt = 0; ntt < 4; ntt++) {
        int d = nh * 32 + ntt * 8 + 2 * (lane & 3);
        size_t base0 = ((size_t)(b * SEQ + n0 + row0)) * DIM + h * HDIM + d;
        size_t base1 = ((size_t)(b * SEQ + n0 + row0 + 8)) * DIM + h * HDIM + d;
        out[base0]     = oacc[ntt][0] * inv0;
        out[base0 + 1] = oacc[ntt][1] * inv0;
        out[base1]     = oacc[ntt][2] * inv1;
        out[base1 + 1] = oacc[ntt][3] * inv1;
    }
}

// ============================ launch ============================
extern "C" void kernel_launch(void* const* d_in, const int* in_sizes, int n_in,
                              void* d_out, int out_size)
{
    const float* x      = (const float*)d_in[0];
    const float* ln1_g  = (const float*)d_in[1];
    const float* ln1_b  = (const float*)d_in[2];
    const float* ln2_g  = (const float*)d_in[3];
    const float* ln2_b  = (const float*)d_in[4];
    const float* qkv_w  = (const float*)d_in[5];
    const float* qkv_b  = (const float*)d_in[6];
    const float* proj_w = (const float*)d_in[7];
    const float* proj_b = (const float*)d_in[8];
    const float* fc1_w  = (const float*)d_in[9];
    const float* fc1_b  = (const float*)d_in[10];
    const float* fc2_w  = (const float*)d_in[11];
    const float* fc2_b  = (const float*)d_in[12];
    const float* attn_a = (const float*)d_in[13];
    const float* attn_b = (const float*)d_in[14];
    const float* attn_c = (const float*)d_in[15];
    const float* gelu_a = (const float*)d_in[16];
    const float* gelu_b = (const float*)d_in[17];
    const float* gelu_c = (const float*)d_in[18];
    float* out = (float*)d_out;

    void *p_h, *p_q, *p_k, *p_v, *p_ao, *p_x1, *p_u;
    cudaGetSymbolAddress(&p_h,  g_h);
    cudaGetSymbolAddress(&p_q,  g_q);
    cudaGetSymbolAddress(&p_k,  g_k);
    cudaGetSymbolAddress(&p_v,  g_v);
    cudaGetSymbolAddress(&p_ao, g_attnout);
    cudaGetSymbolAddress(&p_x1, g_x1);
    cudaGetSymbolAddress(&p_u,  g_u);
    float* h_  = (float*)p_h;
    float* q_  = (float*)p_q;
    float* k_  = (float*)p_k;
    float* v_  = (float*)p_v;
    float* ao_ = (float*)p_ao;
    float* x1_ = (float*)p_x1;
    float* u_  = (float*)p_u;

    static int attr_set = 0;
    if (!attr_set) {
        cudaFuncSetAttribute(attn_mma, cudaFuncAttributeMaxDynamicSharedMemorySize, ATTN_SMEM);
        cudaFuncSetAttribute(mma_gemm<1>, cudaFuncAttributeMaxDynamicSharedMemorySize, GEMM_SMEM);
        cudaFuncSetAttribute(mma_gemm<2>, cudaFuncAttributeMaxDynamicSharedMemorySize, GEMM_SMEM);
        cudaFuncSetAttribute(mma_gemm<3>, cudaFuncAttributeMaxDynamicSharedMemorySize, GEMM_SMEM);
        attr_set = 1;
    }

    ln_kernel<<<TOK, 192>>>(x, ln1_g, ln1_b, h_);
    mma_gemm<1><<<dim3(3 * DIM / 128, TOK / 128), 256, GEMM_SMEM>>>(
        h_, qkv_w, qkv_b, nullptr, nullptr, TOK, 3 * DIM, DIM,
        q_, k_, v_, nullptr, nullptr, nullptr);
    attn_mma<<<dim3(SEQ / 64, BH), 256, ATTN_SMEM>>>(q_, k_, v_, ao_,
                                                     attn_a, attn_b, attn_c);
    mma_gemm<2><<<dim3(DIM / 128, TOK / 128), 256, GEMM_SMEM>>>(
        ao_, proj_w, proj_b, x, x1_, TOK, DIM, DIM,
        nullptr, nullptr, nullptr, nullptr, nullptr, nullptr);
    ln_kernel<<<TOK, 192>>>(x1_, ln2_g, ln2_b, h_);
    mma_gemm<3><<<dim3(HID / 128, TOK / 128), 256, GEMM_SMEM>>>(
        h_, fc1_w, fc1_b, nullptr, u_, TOK, HID, DIM,
        nullptr, nullptr, nullptr, gelu_a, gelu_b, gelu_c);
    mma_gemm<2><<<dim3(DIM / 128, TOK / 128), 256, GEMM_SMEM>>>(
        u_, fc2_w, fc2_b, x1_, out, TOK, DIM, HID,
        nullptr, nullptr, nullptr, nullptr, nullptr, nullptr);
}

// round 5
// speedup vs baseline: 3.8990x; 1.0756x over previous
#include <cuda_runtime.h>
#include <cuda_bf16.h>

#define TOK   8192
#define SEQ   2048
#define BATCH 4
#define DIM   768
#define NHEAD 12
#define HDIM  64
#define BH    (BATCH*NHEAD)
#define HID   3072
#define QKSCALE 0.125f
#define LN_EPS 1e-5f

__device__ float g_h[TOK * DIM];
__device__ float g_q[BH * SEQ * HDIM];
__device__ float g_k[BH * SEQ * HDIM];
__device__ float g_v[BH * SEQ * HDIM];
__device__ float g_attnout[TOK * DIM];
__device__ float g_x1[TOK * DIM];
__device__ float g_u[TOK * HID];

__device__ __forceinline__ void mma_tf32(float& d0, float& d1, float& d2, float& d3,
                                         unsigned a0, unsigned a1, unsigned a2, unsigned a3,
                                         unsigned b0, unsigned b1)
{
    asm volatile(
        "mma.sync.aligned.m16n8k8.row.col.f32.tf32.tf32.f32 "
        "{%0,%1,%2,%3},{%4,%5,%6,%7},{%8,%9},{%0,%1,%2,%3};"
        : "+f"(d0), "+f"(d1), "+f"(d2), "+f"(d3)
        : "r"(a0), "r"(a1), "r"(a2), "r"(a3), "r"(b0), "r"(b1));
}

__device__ __forceinline__ void ldsm4(unsigned& r0, unsigned& r1, unsigned& r2, unsigned& r3,
                                      unsigned addr)
{
    asm volatile("ldmatrix.sync.aligned.m8n8.x4.shared.b16 {%0,%1,%2,%3}, [%4];"
        : "=r"(r0), "=r"(r1), "=r"(r2), "=r"(r3) : "r"(addr));
}

__device__ __forceinline__ void cp16(unsigned saddr, const void* gptr) {
    asm volatile("cp.async.cg.shared.global [%0], [%1], 16;" :: "r"(saddr), "l"(gptr));
}
#define CP_COMMIT() asm volatile("cp.async.commit_group;")
#define CP_WAIT(n)  asm volatile("cp.async.wait_group %0;" :: "n"(n))
#define BAR_PAIR(id) asm volatile("bar.sync %0, 64;" :: "r"(id) : "memory")

// ============================ LayerNorm (vectorized) ============================
__global__ __launch_bounds__(192) void ln_kernel(
    const float* __restrict__ x, const float* __restrict__ gamma,
    const float* __restrict__ beta, float* __restrict__ out)
{
    int row = blockIdx.x;
    int tid = threadIdx.x;
    const float* xr = x + (size_t)row * DIM;
    float4 v = *(const float4*)(xr + tid * 4);
    float s  = v.x + v.y + v.z + v.w;
    float s2 = v.x * v.x + v.y * v.y + v.z * v.z + v.w * v.w;
    #pragma unroll
    for (int o = 16; o; o >>= 1) {
        s  += __shfl_xor_sync(0xffffffffu, s,  o);
        s2 += __shfl_xor_sync(0xffffffffu, s2, o);
    }
    __shared__ float rs[6], rs2[6];
    int lane = tid & 31, wid = tid >> 5;
    if (lane == 0) { rs[wid] = s; rs2[wid] = s2; }
    __syncthreads();
    float ts = 0.f, ts2 = 0.f;
    #pragma unroll
    for (int i = 0; i < 6; i++) { ts += rs[i]; ts2 += rs2[i]; }
    float mean = ts * (1.0f / DIM);
    float var  = ts2 * (1.0f / DIM) - mean * mean;
    float inv  = rsqrtf(var + LN_EPS);
    float4 g = *(const float4*)(gamma + tid * 4);
    float4 b = *(const float4*)(beta + tid * 4);
    float4 o;
    o.x = (v.x - mean) * inv * g.x + b.x;
    o.y = (v.y - mean) * inv * g.y + b.y;
    o.z = (v.z - mean) * inv * g.z + b.z;
    o.w = (v.w - mean) * inv * g.w + b.w;
    *(float4*)(out + (size_t)row * DIM + tid * 4) = o;
}

// ============================ TF32 GEMM, k32 tiles, 3-stage cp.async ============================
#define AS_W 36
#define BS_W 136
#define AS_STAGE (128 * AS_W)
#define BS_STAGE (32 * BS_W)
#define STAGE_W  (AS_STAGE + BS_STAGE)
#define GEMM_SMEM (3 * STAGE_W * 4)

template <int EPI>
__global__ __launch_bounds__(256, 2) void mma_gemm(
    const float* __restrict__ A, const float* __restrict__ W,
    const float* __restrict__ bias, const float* __restrict__ res,
    float* __restrict__ C, int M, int N, int K,
    float* __restrict__ qo, float* __restrict__ ko, float* __restrict__ vo,
    const float* __restrict__ c0, const float* __restrict__ c1,
    const float* __restrict__ c2)
{
    extern __shared__ unsigned smem[];

    const int tid  = threadIdx.x;
    const int lane = tid & 31;
    const int w    = tid >> 5;
    const int wm   = w >> 2;
    const int wn   = w & 3;
    const int bx = blockIdx.x, by = blockIdx.y;

    const int arow = tid >> 3, ac4 = tid & 7;   // A: 32 rows/pass x k32
    const int brow = tid >> 5, bc4 = tid & 31;  // B: 8 rows/pass x 128 cols

    const float* Ag = A + (size_t)(by * 128 + arow) * K + ac4 * 4;
    const float* Bg = W + (size_t)brow * N + bx * 128 + bc4 * 4;

    const unsigned sbase = (unsigned)__cvta_generic_to_shared(smem);

    const int nt = K >> 5;

    // prologue: stages 0,1
    #pragma unroll
    for (int t = 0; t < 2; t++) {
        unsigned sb = sbase + t * STAGE_W * 4;
        #pragma unroll
        for (int p = 0; p < 4; p++) {
            cp16(sb + ((arow + p * 32) * AS_W + ac4 * 4) * 4,
                 Ag + (size_t)p * 32 * K + t * 32);
            cp16(sb + (AS_STAGE + (brow + p * 8) * BS_W + bc4 * 4) * 4,
                 Bg + (size_t)(t * 32 + p * 8) * N);
        }
        CP_COMMIT();
    }

    float acc[4][4][4];
    #pragma unroll
    for (int i = 0; i < 4; i++)
        #pragma unroll
        for (int j = 0; j < 4; j++)
            #pragma unroll
            for (int r = 0; r < 4; r++) acc[i][j][r] = 0.f;

    const unsigned a_laneoff = (((lane & 7) + ((lane >> 3) & 1) * 8) * AS_W + (lane >> 4) * 4) * 4;

    int stage = 0;
    for (int t = 0; t < nt; t++) {
        CP_WAIT(1);
        __syncthreads();            // single barrier per k32 tile
        if (t + 2 < nt) {
            int s2 = stage + 2; if (s2 >= 3) s2 -= 3;
            unsigned sb = sbase + s2 * STAGE_W * 4;
            int tt = t + 2;
            #pragma unroll
            for (int p = 0; p < 4; p++) {
                cp16(sb + ((arow + p * 32) * AS_W + ac4 * 4) * 4,
                     Ag + (size_t)p * 32 * K + tt * 32);
                cp16(sb + (AS_STAGE + (brow + p * 8) * BS_W + bc4 * 4) * 4,
                     Bg + (size_t)(tt * 32 + p * 8) * N);
            }
        }
        CP_COMMIT();

        unsigned sA = sbase + stage * STAGE_W * 4;
        const unsigned* BsS = smem + stage * STAGE_W + AS_STAGE;
        #pragma unroll
        for (int kk = 0; kk < 32; kk += 8) {
            unsigned af[4][4], bf[4][2];
            #pragma unroll
            for (int mt = 0; mt < 4; mt++) {
                unsigned addr = sA + ((wm * 64 + mt * 16) * AS_W + kk) * 4 + a_laneoff;
                ldsm4(af[mt][0], af[mt][1], af[mt][2], af[mt][3], addr);
            }
            #pragma unroll
            for (int ntt = 0; ntt < 4; ntt++) {
                int col = wn * 32 + ntt * 8 + (lane >> 2);
                bf[ntt][0] = BsS[(kk + (lane & 3)) * BS_W + col];
                bf[ntt][1] = BsS[(kk + (lane & 3) + 4) * BS_W + col];
            }
            #pragma unroll
            for (int mt = 0; mt < 4; mt++)
                #pragma unroll
                for (int ntt = 0; ntt < 4; ntt++)
                    mma_tf32(acc[mt][ntt][0], acc[mt][ntt][1], acc[mt][ntt][2], acc[mt][ntt][3],
                             af[mt][0], af[mt][1], af[mt][2], af[mt][3],
                             bf[ntt][0], bf[ntt][1]);
        }
        stage++; if (stage == 3) stage = 0;
    }

    float ga = 0.f, gb = 0.f, gc = 0.f;
    if (EPI == 3) { ga = *c0; gb = *c1; gc = *c2; }

    #pragma unroll
    for (int mt = 0; mt < 4; mt++) {
        #pragma unroll
        for (int ntt = 0; ntt < 4; ntt++) {
            int r0  = by * 128 + wm * 64 + mt * 16 + (lane >> 2);
            int cc0 = bx * 128 + wn * 32 + ntt * 8 + 2 * (lane & 3);
            #pragma unroll
            for (int half = 0; half < 2; half++) {
                int r = r0 + half * 8;
                float v0 = acc[mt][ntt][half * 2 + 0] + bias[cc0];
                float v1 = acc[mt][ntt][half * 2 + 1] + bias[cc0 + 1];
                if (EPI == 1) {
                    int which = cc0 / DIM;
                    int jj = cc0 - which * DIM;
                    int h = jj >> 6, d = jj & 63;
                    int b = r >> 11, n = r & 2047;
                    float* dst = (which == 0) ? qo : (which == 1) ? ko : vo;
                    if (which == 0) { v0 *= QKSCALE; v1 *= QKSCALE; }
                    size_t base = (((size_t)(b * NHEAD + h) * SEQ) + n) * HDIM + d;
                    dst[base] = v0; dst[base + 1] = v1;
                } else if (EPI == 2) {
                    size_t base = (size_t)r * N + cc0;
                    C[base]     = v0 + res[base];
                    C[base + 1] = v1 + res[base + 1];
                } else if (EPI == 3) {
                    size_t base = (size_t)r * N + cc0;
                    C[base]     = fmaf(v0, fmaf(ga, v0, gb), gc);
                    C[base + 1] = fmaf(v1, fmaf(ga, v1, gb), gc);
                } else {
                    size_t base = (size_t)r * N + cc0;
                    C[base] = v0; C[base + 1] = v1;
                }
            }
        }
    }
}

// ============================ Polynomial attention ============================
#define KS_W 68
#define VS_W 72
#define KS_T (64 * KS_W)
#define VS_T (64 * VS_W)
#define ATTN_SMEM ((2 * KS_T + 2 * VS_T + 64 * 68) * 4)

__global__ __launch_bounds__(256, 2) void attn_mma(
    const float* __restrict__ Q, const float* __restrict__ Kg,
    const float* __restrict__ Vg, float* __restrict__ out,
    const float* __restrict__ pa, const float* __restrict__ pb,
    const float* __restrict__ pc)
{
    extern __shared__ unsigned dsm[];
    unsigned* Ks = dsm;
    unsigned* Vs = dsm + 2 * KS_T;
    unsigned* Ss = dsm + 2 * KS_T + 2 * VS_T;
    __shared__ float rsums[64];

    const int tid  = threadIdx.x;
    const int lane = tid & 31;
    const int w    = tid >> 5;
    const int mt   = w >> 1;
    const int nh   = w & 1;
    const int bh   = blockIdx.y;
    const int n0   = blockIdx.x * 64;

    const float* Qb = Q  + (size_t)bh * SEQ * HDIM;
    const float* Kb = Kg + (size_t)bh * SEQ * HDIM;
    const float* Vb = Vg + (size_t)bh * SEQ * HDIM;

    const float aa = *pa, bb = *pb, cc = *pc;

    if (tid < 64) rsums[tid] = 0.f;

    const int grow = tid >> 4;
    const int gc4  = tid & 15;

    const unsigned sKs = (unsigned)__cvta_generic_to_shared(Ks);
    const unsigned sVs = (unsigned)__cvta_generic_to_shared(Vs);
    const unsigned sSs = (unsigned)__cvta_generic_to_shared(Ss);

    #pragma unroll
    for (int it = 0; it < 4; it++) {
        int r = it * 16 + grow;
        cp16(sSs + (r * 68 + gc4 * 4) * 4, Qb + (size_t)(n0 + r) * HDIM + gc4 * 4);
    }
    CP_COMMIT();
    #pragma unroll
    for (int t = 0; t < 2; t++) {
        #pragma unroll
        for (int it = 0; it < 4; it++) {
            int r = it * 16 + grow;
            cp16(sKs + (t * KS_T + r * KS_W + gc4 * 4) * 4,
                 Kb + (size_t)(t * 64 + r) * HDIM + gc4 * 4);
            cp16(sVs + (t * VS_T + r * VS_W + gc4 * 4) * 4,
                 Vb + (size_t)(t * 64 + r) * HDIM + gc4 * 4);
        }
        CP_COMMIT();
    }
    CP_WAIT(2);
    __syncthreads();

    const unsigned a_laneoff = (((lane & 7) + ((lane >> 3) & 1) * 8) * 68 + (lane >> 4) * 4) * 4;
    const unsigned b_laneoff = (((lane & 7) + ((lane >> 4) & 1) * 8) * KS_W + ((lane >> 3) & 1) * 4) * 4;

    unsigned qf[8][4];
    #pragma unroll
    for (int kk = 0; kk < 8; kk++) {
        unsigned addr = sSs + (mt * 16 * 68 + kk * 8) * 4 + a_laneoff;
        ldsm4(qf[kk][0], qf[kk][1], qf[kk][2], qf[kk][3], addr);
    }

    float oacc[4][4];
    #pragma unroll
    for (int ntt = 0; ntt < 4; ntt++)
        #pragma unroll
        for (int r = 0; r < 4; r++) oacc[ntt][r] = 0.f;
    float rs0 = 0.f, rs1 = 0.f;

    for (int m = 0; m < 32; m++) {
        const int buf = m & 1;
        CP_WAIT(1);
        __syncthreads();       // (a)

        float sacc[4][4];
        #pragma unroll
        for (int ntt = 0; ntt < 4; ntt++)
            #pragma unroll
            for (int r = 0; r < 4; r++) sacc[ntt][r] = 0.f;

        unsigned kbase = sKs + buf * KS_T * 4;
        #pragma unroll
        for (int kk = 0; kk < 8; kk++) {
            unsigned bf[4][2];
            #pragma unroll
            for (int p = 0; p < 2; p++) {
                unsigned addr = kbase + ((nh * 32 + p * 16) * KS_W + kk * 8) * 4 + b_laneoff;
                ldsm4(bf[2 * p][0], bf[2 * p][1], bf[2 * p + 1][0], bf[2 * p + 1][1], addr);
            }
            #pragma unroll
            for (int ntt = 0; ntt < 4; ntt++)
                mma_tf32(sacc[ntt][0], sacc[ntt][1], sacc[ntt][2], sacc[ntt][3],
                         qf[kk][0], qf[kk][1], qf[kk][2], qf[kk][3],
                         bf[ntt][0], bf[ntt][1]);
        }

        #pragma unroll
        for (int ntt = 0; ntt < 4; ntt++) {
            #pragma unroll
            for (int r = 0; r < 4; r++) {
                float t = sacc[ntt][r];
                t = fmaf(t, fmaf(aa, t, bb), cc);
                t = fmaxf(t, 1e-6f);
                sacc[ntt][r] = t;
                if (r < 2) rs0 += t; else rs1 += t;
            }
        }

        #pragma unroll
        for (int ntt = 0; ntt < 4; ntt++) {
            int row = mt * 16 + (lane >> 2);
            int col = nh * 32 + ntt * 8 + 2 * (lane & 3);
            uint2 u0 = make_uint2(__float_as_uint(sacc[ntt][0]), __float_as_uint(sacc[ntt][1]));
            uint2 u1 = make_uint2(__float_as_uint(sacc[ntt][2]), __float_as_uint(sacc[ntt][3]));
            *(uint2*)&Ss[row * 68 + col]       = u0;
            *(uint2*)&Ss[(row + 8) * 68 + col] = u1;
        }
        BAR_PAIR(1 + mt);      // (b): only the 2 warps sharing rows mt*16..+15 exchange f(S)

        const unsigned* Vbuf = Vs + buf * VS_T;
        #pragma unroll
        for (int kk = 0; kk < 8; kk++) {
            unsigned af[4];
            unsigned addr = sSs + (mt * 16 * 68 + kk * 8) * 4 + a_laneoff;
            ldsm4(af[0], af[1], af[2], af[3], addr);
            unsigned bfv[4][2];
            #pragma unroll
            for (int ntt = 0; ntt < 4; ntt++) {
                int dcol = nh * 32 + ntt * 8 + (lane >> 2);
                bfv[ntt][0] = Vbuf[(kk * 8 + (lane & 3)) * VS_W + dcol];
                bfv[ntt][1] = Vbuf[(kk * 8 + (lane & 3) + 4) * VS_W + dcol];
            }
            #pragma unroll
            for (int ntt = 0; ntt < 4; ntt++)
                mma_tf32(oacc[ntt][0], oacc[ntt][1], oacc[ntt][2], oacc[ntt][3],
                         af[0], af[1], af[2], af[3],
                         bfv[ntt][0], bfv[ntt][1]);
        }
        __syncthreads();       // (c): all reads of buf done before cp overwrites it

        if (m + 2 < 32) {
            int tt = m + 2;
            #pragma unroll
            for (int it = 0; it < 4; it++) {
                int r = it * 16 + grow;
                cp16(sKs + (buf * KS_T + r * KS_W + gc4 * 4) * 4,
                     Kb + (size_t)(tt * 64 + r) * HDIM + gc4 * 4);
                cp16(sVs + (buf * VS_T + r * VS_W + gc4 * 4) * 4,
                     Vb + (size_t)(tt * 64 + r) * HDIM + gc4 * 4);
            }
        }
        CP_COMMIT();
    }

    rs0 += __shfl_xor_sync(0xffffffffu, rs0, 1);
    rs0 += __shfl_xor_sync(0xffffffffu, rs0, 2);
    rs1 += __shfl_xor_sync(0xffffffffu, rs1, 1);
    rs1 += __shfl_xor_sync(0xffffffffu, rs1, 2);
    if ((lane & 3) == 0) {
        atomicAdd(&rsums[mt * 16 + (lane >> 2)], rs0);
        atomicAdd(&rsums[mt * 16 + (lane >> 2) + 8], rs1);
    }
    __syncthreads();

    int b = bh / NHEAD, h = bh % NHEAD;
    int row0 = mt * 16 + (lane >> 2);
    float inv0 = 1.0f / (rsums[row0] + 1e-8f);
    float inv1 = 1.0f / (rsums[row0 + 8] + 1e-8f);
    #pragma unroll
    for (int ntt = 0; ntt < 4; ntt++) {
        int d = nh * 32 + ntt * 8 + 2 * (lane & 3);
        size_t base0 = ((size_t)(b * SEQ + n0 + row0)) * DIM + h * HDIM + d;
        size_t base1 = ((size_t)(b * SEQ + n0 + row0 + 8)) * DIM + h * HDIM + d;
        out[base0]     = oacc[ntt][0] * inv0;
        out[base0 + 1] = oacc[ntt][1] * inv0;
        out[base1]     = oacc[ntt][2] * inv1;
        out[base1 + 1] = oacc[ntt][3] * inv1;
    }
}

// ============================ launch ============================
extern "C" void kernel_launch(void* const* d_in, const int* in_sizes, int n_in,
                              void* d_out, int out_size)
{
    const float* x      = (const float*)d_in[0];
    const float* ln1_g  = (const float*)d_in[1];
    const float* ln1_b  = (const float*)d_in[2];
    const float* ln2_g  = (const float*)d_in[3];
    const float* ln2_b  = (const float*)d_in[4];
    const float* qkv_w  = (const float*)d_in[5];
    const float* qkv_b  = (const float*)d_in[6];
    const float* proj_w = (const float*)d_in[7];
    const float* proj_b = (const float*)d_in[8];
    const float* fc1_w  = (const float*)d_in[9];
    const float* fc1_b  = (const float*)d_in[10];
    const float* fc2_w  = (const float*)d_in[11];
    const float* fc2_b  = (const float*)d_in[12];
    const float* attn_a = (const float*)d_in[13];
    const float* attn_b = (const float*)d_in[14];
    const float* attn_c = (const float*)d_in[15];
    const float* gelu_a = (const float*)d_in[16];
    const float* gelu_b = (const float*)d_in[17];
    const float* gelu_c = (const float*)d_in[18];
    float* out = (float*)d_out;

    void *p_h, *p_q, *p_k, *p_v, *p_ao, *p_x1, *p_u;
    cudaGetSymbolAddress(&p_h,  g_h);
    cudaGetSymbolAddress(&p_q,  g_q);
    cudaGetSymbolAddress(&p_k,  g_k);
    cudaGetSymbolAddress(&p_v,  g_v);
    cudaGetSymbolAddress(&p_ao, g_attnout);
    cudaGetSymbolAddress(&p_x1, g_x1);
    cudaGetSymbolAddress(&p_u,  g_u);
    float* h_  = (float*)p_h;
    float* q_  = (float*)p_q;
    float* k_  = (float*)p_k;
    float* v_  = (float*)p_v;
    float* ao_ = (float*)p_ao;
    float* x1_ = (float*)p_x1;
    float* u_  = (float*)p_u;

    static int attr_set = 0;
    if (!attr_set) {
        cudaFuncSetAttribute(attn_mma, cudaFuncAttributeMaxDynamicSharedMemorySize, ATTN_SMEM);
        cudaFuncSetAttribute(mma_gemm<1>, cudaFuncAttributeMaxDynamicSharedMemorySize, GEMM_SMEM);
        cudaFuncSetAttribute(mma_gemm<2>, cudaFuncAttributeMaxDynamicSharedMemorySize, GEMM_SMEM);
        cudaFuncSetAttribute(mma_gemm<3>, cudaFuncAttributeMaxDynamicSharedMemorySize, GEMM_SMEM);
        attr_set = 1;
    }

    ln_kernel<<<TOK, 192>>>(x, ln1_g, ln1_b, h_);
    mma_gemm<1><<<dim3(3 * DIM / 128, TOK / 128), 256, GEMM_SMEM>>>(
        h_, qkv_w, qkv_b, nullptr, nullptr, TOK, 3 * DIM, DIM,
        q_, k_, v_, nullptr, nullptr, nullptr);
    attn_mma<<<dim3(SEQ / 64, BH), 256, ATTN_SMEM>>>(q_, k_, v_, ao_,
                                                     attn_a, attn_b, attn_c);
    mma_gemm<2><<<dim3(DIM / 128, TOK / 128), 256, GEMM_SMEM>>>(
        ao_, proj_w, proj_b, x, x1_, TOK, DIM, DIM,
        nullptr, nullptr, nullptr, nullptr, nullptr, nullptr);
    ln_kernel<<<TOK, 192>>>(x1_, ln2_g, ln2_b, h_);
    mma_gemm<3><<<dim3(HID / 128, TOK / 128), 256, GEMM_SMEM>>>(
        h_, fc1_w, fc1_b, nullptr, u_, TOK, HID, DIM,
        nullptr, nullptr, nullptr, gelu_a, gelu_b, gelu_c);
    mma_gemm<2><<<dim3(DIM / 128, TOK / 128), 256, GEMM_SMEM>>>(
        u_, fc2_w, fc2_b, x1_, out, TOK, DIM, HID,
        nullptr, nullptr, nullptr, nullptr, nullptr, nullptr);
}